// round 3
// baseline (speedup 1.0000x reference)
#include <cuda_runtime.h>
#include <cstdint>

#define N_NODES    100000
#define N_EDGES    640000
#define D_IN       128
#define HIDDEN     256
#define OUT_D      256
#define NUM_GRAPHS 256

// ---------------- scratch (device globals; no allocs allowed) ----------------
__device__ __align__(16) float g_agg1[N_NODES * D_IN];    // mean-agg of x (inv_cnt folded)
__device__ __align__(16) float g_h1  [N_NODES * HIDDEN];  // relu layer-1 output
__device__ __align__(16) float g_agg2[N_NODES * HIDDEN];  // mean-agg of h1 (inv_cnt folded)
__device__ __align__(16) float g_cnt [N_NODES];
__device__ __align__(16) float g_inv [N_NODES];
__device__ __align__(16) float g_Ph  [NUM_GRAPHS * HIDDEN]; // segsum(h1)
__device__ __align__(16) float g_Pa  [NUM_GRAPHS * HIDDEN]; // segsum(agg2)
__device__ __align__(16) float g_ng  [NUM_GRAPHS];          // nodes per graph

__device__ __forceinline__ void red_add_v4(float* p, float4 v) {
    asm volatile("red.global.add.v4.f32 [%0], {%1,%2,%3,%4};"
                 :: "l"(p), "f"(v.x), "f"(v.y), "f"(v.z), "f"(v.w)
                 : "memory");
}

// ---------------- zero scratch accumulators ----------------
__global__ void zero_kernel() {
    size_t i = (size_t)blockIdx.x * blockDim.x + threadIdx.x;
    size_t stride = (size_t)gridDim.x * blockDim.x;
    float4 z = make_float4(0.f, 0.f, 0.f, 0.f);
    float4* a1 = (float4*)g_agg1;
    float4* a2 = (float4*)g_agg2;
    for (size_t j = i; j < (size_t)N_NODES * D_IN / 4;  j += stride) a1[j] = z;
    for (size_t j = i; j < (size_t)N_NODES * HIDDEN / 4; j += stride) a2[j] = z;
    for (size_t j = i; j < N_NODES; j += stride) g_cnt[j] = 0.f;
}

// ---------------- in-degree counts ----------------
__global__ void count_kernel(const int* __restrict__ ei) {
    int e = blockIdx.x * blockDim.x + threadIdx.x;
    if (e < N_EDGES) {
        int dst = ei[N_EDGES + e];
        atomicAdd(&g_cnt[dst], 1.0f);
    }
}

__global__ void inv_kernel() {
    int i = blockIdx.x * blockDim.x + threadIdx.x;
    if (i < N_NODES) g_inv[i] = 1.0f / fmaxf(g_cnt[i], 1.0f);
}

// ---------------- layer-1 scatter: agg1[dst] += x[src] * inv_cnt[dst] --------
// one warp per edge; 128 floats = 1 float4 per lane
__global__ __launch_bounds__(256) void scatter1_kernel(const float* __restrict__ x,
                                                       const int* __restrict__ ei) {
    int w = (blockIdx.x * blockDim.x + threadIdx.x) >> 5;
    int lane = threadIdx.x & 31;
    if (w >= N_EDGES) return;
    int src = ei[w];
    int dst = ei[N_EDGES + w];
    float s = g_inv[dst];
    float4 v = ((const float4*)(x + (size_t)src * D_IN))[lane];
    v.x *= s; v.y *= s; v.z *= s; v.w *= s;
    red_add_v4(g_agg1 + (size_t)dst * D_IN + lane * 4, v);
}

// ---------------- layer-2 scatter: agg2[dst] += h1[src] * inv_cnt[dst] -------
// one warp per edge; 256 floats = 2 float4 per lane
__global__ __launch_bounds__(256) void scatter2_kernel(const int* __restrict__ ei) {
    int w = (blockIdx.x * blockDim.x + threadIdx.x) >> 5;
    int lane = threadIdx.x & 31;
    if (w >= N_EDGES) return;
    int src = ei[w];
    int dst = ei[N_EDGES + w];
    float s = g_inv[dst];
    const float4* h = (const float4*)(g_h1 + (size_t)src * HIDDEN);
    float4 v0 = h[lane];
    float4 v1 = h[lane + 32];
    v0.x *= s; v0.y *= s; v0.z *= s; v0.w *= s;
    v1.x *= s; v1.y *= s; v1.z *= s; v1.w *= s;
    float* o = g_agg2 + (size_t)dst * HIDDEN;
    red_add_v4(o + lane * 4, v0);
    red_add_v4(o + 128 + lane * 4, v1);
}

// ---------------- fused layer-1 GEMM + bias + relu ----------------
// h1 = relu( [agg1 | x] (100000 x 256)  @  [W1_l ; W1_r] (256 x 256)  + b1 )
// Classic SGEMM: 128x128 tile, BK=16, 256 threads, 8x8 per thread, double-buffered.
#define BM 128
#define BN 128
#define BK 16

__global__ __launch_bounds__(256) void gemm1_kernel(const float* __restrict__ x,
                                                    const float* __restrict__ W1l,
                                                    const float* __restrict__ W1r,
                                                    const float* __restrict__ b1) {
    __shared__ float As[2][BK * BM];  // transposed: As[k][m]
    __shared__ float Bs[2][BK * BN];  // Bs[k][n]

    const int tid = threadIdx.x;
    const int tx = tid & 15;   // n
    const int ty = tid >> 4;   // m
    const int rowBase = blockIdx.x * BM;
    const int colBase = blockIdx.y * BN;

    const int a_lr = tid >> 2;  // 0..63
    const int a_c4 = tid & 3;   // 0..3

    float acc[8][8];
#pragma unroll
    for (int i = 0; i < 8; i++)
#pragma unroll
        for (int j = 0; j < 8; j++) acc[i][j] = 0.f;

    float4 aR[2], bR[2];

    // ---- fetch chunk kc into registers ----
    auto fetch = [&](int kc) {
        const float* Asrc = (kc < 8) ? g_agg1 : x;
        const float* Bsrc = (kc < 8) ? W1l : W1r;
        int kb = (kc & 7) * BK;
#pragma unroll
        for (int p = 0; p < 2; p++) {
            int r = rowBase + p * 64 + a_lr;
            r = min(r, N_NODES - 1);
            aR[p] = *(const float4*)(Asrc + (size_t)r * D_IN + kb + a_c4 * 4);
        }
#pragma unroll
        for (int q = 0; q < 2; q++) {
            int lin = q * 256 + tid;
            int r = lin >> 5;        // 0..15
            int c4 = lin & 31;       // 0..31
            bR[q] = *(const float4*)(Bsrc + (size_t)(kb + r) * HIDDEN + colBase + c4 * 4);
        }
    };

    auto store = [&](int buf) {
#pragma unroll
        for (int p = 0; p < 2; p++) {
            int m = p * 64 + a_lr;
            int k0 = a_c4 * 4;
            As[buf][(k0 + 0) * BM + m] = aR[p].x;
            As[buf][(k0 + 1) * BM + m] = aR[p].y;
            As[buf][(k0 + 2) * BM + m] = aR[p].z;
            As[buf][(k0 + 3) * BM + m] = aR[p].w;
        }
#pragma unroll
        for (int q = 0; q < 2; q++) {
            int lin = q * 256 + tid;
            int r = lin >> 5;
            int c4 = lin & 31;
            *(float4*)&Bs[buf][r * BN + c4 * 4] = bR[q];
        }
    };

    fetch(0);
    store(0);
    __syncthreads();

    int buf = 0;
    for (int kc = 0; kc < 16; kc++) {
        if (kc < 15) fetch(kc + 1);
#pragma unroll
        for (int kk = 0; kk < BK; kk++) {
            float af[8], bf[8];
            *(float4*)&af[0] = *(const float4*)&As[buf][kk * BM + ty * 8];
            *(float4*)&af[4] = *(const float4*)&As[buf][kk * BM + ty * 8 + 4];
            *(float4*)&bf[0] = *(const float4*)&Bs[buf][kk * BN + tx * 8];
            *(float4*)&bf[4] = *(const float4*)&Bs[buf][kk * BN + tx * 8 + 4];
#pragma unroll
            for (int i = 0; i < 8; i++)
#pragma unroll
                for (int j = 0; j < 8; j++) acc[i][j] += af[i] * bf[j];
        }
        if (kc < 15) {
            buf ^= 1;
            store(buf);
            __syncthreads();
        }
    }

    float bias[8];
#pragma unroll
    for (int j = 0; j < 8; j++) bias[j] = b1[colBase + tx * 8 + j];

#pragma unroll
    for (int i = 0; i < 8; i++) {
        int r = rowBase + ty * 8 + i;
        if (r < N_NODES) {
            float4 o0, o1;
            o0.x = fmaxf(acc[i][0] + bias[0], 0.f);
            o0.y = fmaxf(acc[i][1] + bias[1], 0.f);
            o0.z = fmaxf(acc[i][2] + bias[2], 0.f);
            o0.w = fmaxf(acc[i][3] + bias[3], 0.f);
            o1.x = fmaxf(acc[i][4] + bias[4], 0.f);
            o1.y = fmaxf(acc[i][5] + bias[5], 0.f);
            o1.z = fmaxf(acc[i][6] + bias[6], 0.f);
            o1.w = fmaxf(acc[i][7] + bias[7], 0.f);
            float* dst = g_h1 + (size_t)r * HIDDEN + colBase + tx * 8;
            *(float4*)dst = o0;
            *(float4*)(dst + 4) = o1;
        }
    }
}

// ---------------- pooling: per-graph contiguous segment sums ----------------
__device__ __forceinline__ int lower_bound_i(const int* a, int n, int v) {
    int lo = 0, hi = n;
    while (lo < hi) {
        int mid = (lo + hi) >> 1;
        if (a[mid] < v) lo = mid + 1; else hi = mid;
    }
    return lo;
}

__global__ __launch_bounds__(256) void pool_kernel(const int* __restrict__ batch) {
    int g = blockIdx.x;
    int t = threadIdx.x;
    int start = lower_bound_i(batch, N_NODES, g);
    int end   = lower_bound_i(batch, N_NODES, g + 1);

    float sh = 0.f, sa = 0.f;
    int i = start;
    for (; i + 3 < end; i += 4) {
        float h0 = g_h1[(size_t)(i + 0) * HIDDEN + t];
        float h1v = g_h1[(size_t)(i + 1) * HIDDEN + t];
        float h2 = g_h1[(size_t)(i + 2) * HIDDEN + t];
        float h3 = g_h1[(size_t)(i + 3) * HIDDEN + t];
        float a0 = g_agg2[(size_t)(i + 0) * HIDDEN + t];
        float a1 = g_agg2[(size_t)(i + 1) * HIDDEN + t];
        float a2 = g_agg2[(size_t)(i + 2) * HIDDEN + t];
        float a3 = g_agg2[(size_t)(i + 3) * HIDDEN + t];
        sh += (h0 + h1v) + (h2 + h3);
        sa += (a0 + a1) + (a2 + a3);
    }
    for (; i < end; i++) {
        sh += g_h1[(size_t)i * HIDDEN + t];
        sa += g_agg2[(size_t)i * HIDDEN + t];
    }
    g_Ph[g * HIDDEN + t] = sh;
    g_Pa[g * HIDDEN + t] = sa;
    if (t == 0) g_ng[g] = (float)(end - start);
}

// ---------------- final tiny GEMM: out = Pa@W2l + Ph@W2r + ng*b2 -------------
__global__ __launch_bounds__(256) void final_kernel(const float* __restrict__ W2l,
                                                    const float* __restrict__ W2r,
                                                    const float* __restrict__ b2,
                                                    float* __restrict__ out) {
    __shared__ float pa[HIDDEN], ph[HIDDEN];
    int g = blockIdx.x;
    int t = threadIdx.x;
    pa[t] = g_Pa[g * HIDDEN + t];
    ph[t] = g_Ph[g * HIDDEN + t];
    __syncthreads();
    float acc = g_ng[g] * b2[t];
#pragma unroll 8
    for (int k = 0; k < HIDDEN; k++) {
        acc += pa[k] * W2l[k * OUT_D + t] + ph[k] * W2r[k * OUT_D + t];
    }
    out[g * OUT_D + t] = acc;
}

// ---------------- launch ----------------
extern "C" void kernel_launch(void* const* d_in, const int* in_sizes, int n_in,
                              void* d_out, int out_size) {
    const float* x     = (const float*)d_in[0];
    const int*   ei    = (const int*)d_in[1];    // int32 (JAX x64 disabled)
    const int*   batch = (const int*)d_in[2];    // int32
    const float* W1l   = (const float*)d_in[3];
    const float* b1    = (const float*)d_in[4];
    const float* W1r   = (const float*)d_in[5];
    const float* W2l   = (const float*)d_in[6];
    const float* b2    = (const float*)d_in[7];
    const float* W2r   = (const float*)d_in[8];
    float* out = (float*)d_out;

    zero_kernel<<<2048, 256>>>();
    count_kernel<<<(N_EDGES + 255) / 256, 256>>>(ei);
    inv_kernel<<<(N_NODES + 255) / 256, 256>>>();

    // one warp per edge
    int scatterBlocks = (N_EDGES * 32 + 255) / 256;
    scatter1_kernel<<<scatterBlocks, 256>>>(x, ei);

    dim3 gemmGrid((N_NODES + BM - 1) / BM, HIDDEN / BN);
    gemm1_kernel<<<gemmGrid, 256>>>(x, W1l, W1r, b1);

    scatter2_kernel<<<scatterBlocks, 256>>>(ei);

    pool_kernel<<<NUM_GRAPHS, 256>>>(batch);
    final_kernel<<<NUM_GRAPHS, 256>>>(W2l, W2r, b2, out);
}

// round 4
// speedup vs baseline: 1.4896x; 1.4896x over previous
#include <cuda_runtime.h>
#include <cstdint>

#define N_NODES    100000
#define N_EDGES    640000
#define D_IN       128
#define HIDDEN     256
#define OUT_D      256
#define NUM_GRAPHS 256

// ---------------- scratch (device globals; no allocs allowed) ----------------
__device__ __align__(16) float g_agg1[N_NODES * D_IN];    // mean-agg of x (inv_cnt folded)
__device__ __align__(16) float g_h1  [N_NODES * HIDDEN];  // relu layer-1 output
__device__ __align__(16) float g_agg2[N_NODES * HIDDEN];  // mean-agg of h1 (inv_cnt folded)
__device__ __align__(16) float g_cnt [N_NODES];
__device__ __align__(16) float g_inv [N_NODES];
__device__ __align__(16) float g_Ph  [NUM_GRAPHS * HIDDEN]; // segsum(h1)
__device__ __align__(16) float g_Pa  [NUM_GRAPHS * HIDDEN]; // segsum(agg2)
__device__ __align__(16) float g_ng  [NUM_GRAPHS];          // nodes per graph

__device__ __forceinline__ void red_add_v4(float* p, float4 v) {
    asm volatile("red.global.add.v4.f32 [%0], {%1,%2,%3,%4};"
                 :: "l"(p), "f"(v.x), "f"(v.y), "f"(v.z), "f"(v.w)
                 : "memory");
}

__device__ __forceinline__ float to_tf32(float x) {
    uint32_t u;
    asm("cvt.rna.tf32.f32 %0, %1;" : "=r"(u) : "f"(x));
    return __uint_as_float(u);
}

// ---------------- zero scratch accumulators ----------------
__global__ void zero_kernel() {
    size_t i = (size_t)blockIdx.x * blockDim.x + threadIdx.x;
    size_t stride = (size_t)gridDim.x * blockDim.x;
    float4 z = make_float4(0.f, 0.f, 0.f, 0.f);
    float4* a1 = (float4*)g_agg1;
    float4* a2 = (float4*)g_agg2;
    for (size_t j = i; j < (size_t)N_NODES * D_IN / 4;  j += stride) a1[j] = z;
    for (size_t j = i; j < (size_t)N_NODES * HIDDEN / 4; j += stride) a2[j] = z;
    for (size_t j = i; j < N_NODES; j += stride) g_cnt[j] = 0.f;
}

// ---------------- in-degree counts ----------------
__global__ void count_kernel(const int* __restrict__ ei) {
    int e = blockIdx.x * blockDim.x + threadIdx.x;
    if (e < N_EDGES) {
        int dst = ei[N_EDGES + e];
        atomicAdd(&g_cnt[dst], 1.0f);
    }
}

__global__ void inv_kernel() {
    int i = blockIdx.x * blockDim.x + threadIdx.x;
    if (i < N_NODES) g_inv[i] = 1.0f / fmaxf(g_cnt[i], 1.0f);
}

// ---------------- layer-1 scatter: agg1[dst] += x[src] * inv_cnt[dst] --------
__global__ __launch_bounds__(256) void scatter1_kernel(const float* __restrict__ x,
                                                       const int* __restrict__ ei) {
    int w = (blockIdx.x * blockDim.x + threadIdx.x) >> 5;
    int lane = threadIdx.x & 31;
    if (w >= N_EDGES) return;
    int src = ei[w];
    int dst = ei[N_EDGES + w];
    float s = g_inv[dst];
    float4 v = ((const float4*)(x + (size_t)src * D_IN))[lane];
    v.x *= s; v.y *= s; v.z *= s; v.w *= s;
    red_add_v4(g_agg1 + (size_t)dst * D_IN + lane * 4, v);
}

// ---------------- layer-2 scatter: agg2[dst] += h1[src] * inv_cnt[dst] -------
__global__ __launch_bounds__(256) void scatter2_kernel(const int* __restrict__ ei) {
    int w = (blockIdx.x * blockDim.x + threadIdx.x) >> 5;
    int lane = threadIdx.x & 31;
    if (w >= N_EDGES) return;
    int src = ei[w];
    int dst = ei[N_EDGES + w];
    float s = g_inv[dst];
    const float4* h = (const float4*)(g_h1 + (size_t)src * HIDDEN);
    float4 v0 = h[lane];
    float4 v1 = h[lane + 32];
    v0.x *= s; v0.y *= s; v0.z *= s; v0.w *= s;
    v1.x *= s; v1.y *= s; v1.z *= s; v1.w *= s;
    float* o = g_agg2 + (size_t)dst * HIDDEN;
    red_add_v4(o + lane * 4, v0);
    red_add_v4(o + 128 + lane * 4, v1);
}

// ---------------- fused layer-1 GEMM via TF32 mma.sync ----------------
// h1 = relu( [agg1 | x] (100000 x 256) @ [W1_l ; W1_r] (256 x 256) + b1 )
// CTA tile 128x128, BK=16 double-buffered, 8 warps (4m x 2n), warp tile 32x64.
// mma.sync.aligned.m16n8k8.row.col.f32.tf32.tf32.f32
#define BM 128
#define BN 128
#define BK 16
#define A_PITCH 20    // (16+4): frag LDS bank = (20*g + t) % 32, all 32 distinct
#define B_PITCH 136   // (128+8): frag LDS bank = (8*t + g) % 32, all 32 distinct

__global__ __launch_bounds__(256, 2) void gemm1_tc_kernel(const float* __restrict__ x,
                                                          const float* __restrict__ W1l,
                                                          const float* __restrict__ W1r,
                                                          const float* __restrict__ b1) {
    __shared__ float As[2][BM][A_PITCH];   // [m][k], tf32-rounded
    __shared__ float Bs[2][BK][B_PITCH];   // [k][n], tf32-rounded

    const int tid    = threadIdx.x;
    const int lane   = tid & 31;
    const int wid    = tid >> 5;
    const int warp_m = wid & 3;    // 0..3 -> m offset 32*warp_m
    const int warp_n = wid >> 2;   // 0..1 -> n offset 64*warp_n
    const int g      = lane >> 2;  // groupID 0..7
    const int t      = lane & 3;   // threadID_in_group 0..3

    const int rowBase = blockIdx.x * BM;
    const int colBase = blockIdx.y * BN;

    // fetch indices
    const int a_r  = tid >> 2;  // 0..63
    const int a_c4 = tid & 3;   // 0..3 -> k cols 4c..4c+3

    float acc[2][8][4];
#pragma unroll
    for (int mt = 0; mt < 2; mt++)
#pragma unroll
        for (int nt = 0; nt < 8; nt++)
#pragma unroll
            for (int c = 0; c < 4; c++) acc[mt][nt][c] = 0.f;

    float4 aR[2], bR[2];

    auto fetch = [&](int kc) {   // kc = 0..15, each covers 16 k's
        const float* Asrc = (kc < 8) ? g_agg1 : x;
        const float* Bsrc = (kc < 8) ? W1l : W1r;
        int kb = (kc & 7) * BK;
#pragma unroll
        for (int p = 0; p < 2; p++) {
            int r = rowBase + p * 64 + a_r;
            r = min(r, N_NODES - 1);
            aR[p] = *(const float4*)(Asrc + (size_t)r * D_IN + kb + a_c4 * 4);
        }
#pragma unroll
        for (int q = 0; q < 2; q++) {
            int lin = q * 256 + tid;
            int r  = lin >> 5;   // 0..15
            int c4 = lin & 31;   // 0..31
            bR[q] = *(const float4*)(Bsrc + (size_t)(kb + r) * HIDDEN + colBase + c4 * 4);
        }
    };

    auto store = [&](int buf) {
#pragma unroll
        for (int p = 0; p < 2; p++) {
            float* d = &As[buf][p * 64 + a_r][a_c4 * 4];
            d[0] = to_tf32(aR[p].x); d[1] = to_tf32(aR[p].y);
            d[2] = to_tf32(aR[p].z); d[3] = to_tf32(aR[p].w);
        }
#pragma unroll
        for (int q = 0; q < 2; q++) {
            int lin = q * 256 + tid;
            int r  = lin >> 5;
            int c4 = lin & 31;
            float* d = &Bs[buf][r][c4 * 4];
            d[0] = to_tf32(bR[q].x); d[1] = to_tf32(bR[q].y);
            d[2] = to_tf32(bR[q].z); d[3] = to_tf32(bR[q].w);
        }
    };

    fetch(0);
    store(0);
    __syncthreads();

    int buf = 0;
    for (int kc = 0; kc < 16; kc++) {
        if (kc < 15) fetch(kc + 1);
#pragma unroll
        for (int ks = 0; ks < 2; ks++) {
            const int k0 = ks * 8;
            // A fragments (2 m-tiles): a0(m=g,k=t) a1(m=g+8,k=t) a2(m=g,k=t+4) a3(m=g+8,k=t+4)
            uint32_t af[2][4];
#pragma unroll
            for (int mt = 0; mt < 2; mt++) {
                int m0 = warp_m * 32 + mt * 16;
                af[mt][0] = __float_as_uint(As[buf][m0 + g    ][k0 + t    ]);
                af[mt][1] = __float_as_uint(As[buf][m0 + g + 8][k0 + t    ]);
                af[mt][2] = __float_as_uint(As[buf][m0 + g    ][k0 + t + 4]);
                af[mt][3] = __float_as_uint(As[buf][m0 + g + 8][k0 + t + 4]);
            }
            // B fragments (8 n-tiles): b0(k=t,n=g) b1(k=t+4,n=g)
            uint32_t bf[8][2];
#pragma unroll
            for (int nt = 0; nt < 8; nt++) {
                int n0 = warp_n * 64 + nt * 8;
                bf[nt][0] = __float_as_uint(Bs[buf][k0 + t    ][n0 + g]);
                bf[nt][1] = __float_as_uint(Bs[buf][k0 + t + 4][n0 + g]);
            }
#pragma unroll
            for (int mt = 0; mt < 2; mt++)
#pragma unroll
                for (int nt = 0; nt < 8; nt++) {
                    asm volatile(
                        "mma.sync.aligned.m16n8k8.row.col.f32.tf32.tf32.f32 "
                        "{%0,%1,%2,%3}, {%4,%5,%6,%7}, {%8,%9}, {%0,%1,%2,%3};"
                        : "+f"(acc[mt][nt][0]), "+f"(acc[mt][nt][1]),
                          "+f"(acc[mt][nt][2]), "+f"(acc[mt][nt][3])
                        : "r"(af[mt][0]), "r"(af[mt][1]), "r"(af[mt][2]), "r"(af[mt][3]),
                          "r"(bf[nt][0]), "r"(bf[nt][1]));
                }
        }
        if (kc < 15) {
            buf ^= 1;
            store(buf);
            __syncthreads();
        }
    }

    // epilogue: bias + relu + store. c0(m=g,n=2t) c1(m=g,n=2t+1) c2(m=g+8,..) c3
#pragma unroll
    for (int mt = 0; mt < 2; mt++) {
        int row0 = rowBase + warp_m * 32 + mt * 16 + g;
        int row1 = row0 + 8;
#pragma unroll
        for (int nt = 0; nt < 8; nt++) {
            int col = colBase + warp_n * 64 + nt * 8 + 2 * t;
            float bx = b1[col], by = b1[col + 1];
            if (row0 < N_NODES) {
                float2 o;
                o.x = fmaxf(acc[mt][nt][0] + bx, 0.f);
                o.y = fmaxf(acc[mt][nt][1] + by, 0.f);
                *(float2*)(g_h1 + (size_t)row0 * HIDDEN + col) = o;
            }
            if (row1 < N_NODES) {
                float2 o;
                o.x = fmaxf(acc[mt][nt][2] + bx, 0.f);
                o.y = fmaxf(acc[mt][nt][3] + by, 0.f);
                *(float2*)(g_h1 + (size_t)row1 * HIDDEN + col) = o;
            }
        }
    }
}

// ---------------- pooling: per-graph contiguous segment sums ----------------
__device__ __forceinline__ int lower_bound_i(const int* a, int n, int v) {
    int lo = 0, hi = n;
    while (lo < hi) {
        int mid = (lo + hi) >> 1;
        if (a[mid] < v) lo = mid + 1; else hi = mid;
    }
    return lo;
}

__global__ __launch_bounds__(256) void pool_kernel(const int* __restrict__ batch) {
    int g = blockIdx.x;
    int t = threadIdx.x;
    int start = lower_bound_i(batch, N_NODES, g);
    int end   = lower_bound_i(batch, N_NODES, g + 1);

    float sh = 0.f, sa = 0.f;
    int i = start;
    for (; i + 3 < end; i += 4) {
        float h0 = g_h1[(size_t)(i + 0) * HIDDEN + t];
        float h1v = g_h1[(size_t)(i + 1) * HIDDEN + t];
        float h2 = g_h1[(size_t)(i + 2) * HIDDEN + t];
        float h3 = g_h1[(size_t)(i + 3) * HIDDEN + t];
        float a0 = g_agg2[(size_t)(i + 0) * HIDDEN + t];
        float a1 = g_agg2[(size_t)(i + 1) * HIDDEN + t];
        float a2 = g_agg2[(size_t)(i + 2) * HIDDEN + t];
        float a3 = g_agg2[(size_t)(i + 3) * HIDDEN + t];
        sh += (h0 + h1v) + (h2 + h3);
        sa += (a0 + a1) + (a2 + a3);
    }
    for (; i < end; i++) {
        sh += g_h1[(size_t)i * HIDDEN + t];
        sa += g_agg2[(size_t)i * HIDDEN + t];
    }
    g_Ph[g * HIDDEN + t] = sh;
    g_Pa[g * HIDDEN + t] = sa;
    if (t == 0) g_ng[g] = (float)(end - start);
}

// ---------------- final tiny GEMM: out = Pa@W2l + Ph@W2r + ng*b2 -------------
__global__ __launch_bounds__(256) void final_kernel(const float* __restrict__ W2l,
                                                    const float* __restrict__ W2r,
                                                    const float* __restrict__ b2,
                                                    float* __restrict__ out) {
    __shared__ float pa[HIDDEN], ph[HIDDEN];
    int g = blockIdx.x;
    int t = threadIdx.x;
    pa[t] = g_Pa[g * HIDDEN + t];
    ph[t] = g_Ph[g * HIDDEN + t];
    __syncthreads();
    float acc = g_ng[g] * b2[t];
#pragma unroll 8
    for (int k = 0; k < HIDDEN; k++) {
        acc += pa[k] * W2l[k * OUT_D + t] + ph[k] * W2r[k * OUT_D + t];
    }
    out[g * OUT_D + t] = acc;
}

// ---------------- launch ----------------
extern "C" void kernel_launch(void* const* d_in, const int* in_sizes, int n_in,
                              void* d_out, int out_size) {
    const float* x     = (const float*)d_in[0];
    const int*   ei    = (const int*)d_in[1];    // int32 (JAX x64 disabled)
    const int*   batch = (const int*)d_in[2];    // int32
    const float* W1l   = (const float*)d_in[3];
    const float* b1    = (const float*)d_in[4];
    const float* W1r   = (const float*)d_in[5];
    const float* W2l   = (const float*)d_in[6];
    const float* b2    = (const float*)d_in[7];
    const float* W2r   = (const float*)d_in[8];
    float* out = (float*)d_out;

    zero_kernel<<<2048, 256>>>();
    count_kernel<<<(N_EDGES + 255) / 256, 256>>>(ei);
    inv_kernel<<<(N_NODES + 255) / 256, 256>>>();

    int scatterBlocks = (N_EDGES * 32 + 255) / 256;
    scatter1_kernel<<<scatterBlocks, 256>>>(x, ei);

    dim3 gemmGrid((N_NODES + BM - 1) / BM, HIDDEN / BN);
    gemm1_tc_kernel<<<gemmGrid, 256>>>(x, W1l, W1r, b1);

    scatter2_kernel<<<scatterBlocks, 256>>>(ei);

    pool_kernel<<<NUM_GRAPHS, 256>>>(batch);
    final_kernel<<<NUM_GRAPHS, 256>>>(W2l, W2r, b2, out);
}

// round 5
// speedup vs baseline: 2.2027x; 1.4787x over previous
#include <cuda_runtime.h>
#include <cstdint>

#define N_NODES    100000
#define N_EDGES    640000
#define D_IN       128
#define HIDDEN     256
#define OUT_D      256
#define NUM_GRAPHS 256
#define SCAN_CHUNK 1024
#define NBLK_SCAN  ((N_NODES + SCAN_CHUNK - 1) / SCAN_CHUNK)   // 98

// ---------------- scratch (device globals; no allocs allowed) ----------------
__device__ __align__(16) float g_agg1[N_NODES * D_IN];    // mean-agg of x
__device__ __align__(16) float g_h1  [N_NODES * HIDDEN];  // relu layer-1 output
__device__ __align__(16) float g_agg2[N_NODES * HIDDEN];  // mean-agg of h1
__device__ __align__(16) int   g_cnt [N_NODES];           // in-degree
__device__ __align__(16) float g_inv [N_NODES];
__device__ __align__(16) int   g_off [N_NODES + 1];       // CSR row offsets
__device__ __align__(16) int   g_cur [N_NODES];           // fill cursors
__device__ __align__(16) int   g_csr [N_EDGES];           // src ids grouped by dst
__device__ __align__(16) int   g_bsum [NBLK_SCAN];
__device__ __align__(16) int   g_bbase[NBLK_SCAN];
__device__ __align__(16) float g_Ph  [NUM_GRAPHS * HIDDEN]; // segsum(h1)
__device__ __align__(16) float g_Pa  [NUM_GRAPHS * HIDDEN]; // segsum(agg2)
__device__ __align__(16) float g_ng  [NUM_GRAPHS];          // nodes per graph

__device__ __forceinline__ float to_tf32(float x) {
    uint32_t u;
    asm("cvt.rna.tf32.f32 %0, %1;" : "=r"(u) : "f"(x));
    return __uint_as_float(u);
}

// ---------------- CSR build ----------------
__global__ void zero_cnt_kernel() {
    int i = blockIdx.x * blockDim.x + threadIdx.x;
    if (i < N_NODES) g_cnt[i] = 0;
}

__global__ void count_kernel(const int* __restrict__ ei) {
    int e = blockIdx.x * blockDim.x + threadIdx.x;
    if (e < N_EDGES) atomicAdd(&g_cnt[ei[N_EDGES + e]], 1);
}

__global__ void inv_kernel() {
    int i = blockIdx.x * blockDim.x + threadIdx.x;
    if (i < N_NODES) g_inv[i] = 1.0f / (float)max(g_cnt[i], 1);
}

// per-1024-chunk sums
__global__ __launch_bounds__(256) void scan1_kernel() {
    __shared__ int sm[256];
    int b = blockIdx.x, t = threadIdx.x;
    int s = 0;
#pragma unroll
    for (int k = 0; k < 4; k++) {
        int i = b * SCAN_CHUNK + k * 256 + t;
        if (i < N_NODES) s += g_cnt[i];
    }
    sm[t] = s; __syncthreads();
    for (int o = 128; o > 0; o >>= 1) {
        if (t < o) sm[t] += sm[t + o];
        __syncthreads();
    }
    if (t == 0) g_bsum[b] = sm[0];
}

__global__ void scan2_kernel() {
    if (threadIdx.x == 0) {
        int run = 0;
        for (int b = 0; b < NBLK_SCAN; b++) { g_bbase[b] = run; run += g_bsum[b]; }
        g_off[N_NODES] = N_EDGES;
    }
}

// per-chunk exclusive scan -> offsets + cursors
__global__ __launch_bounds__(256) void scan3_kernel() {
    __shared__ int sm[256];
    int b = blockIdx.x, t = threadIdx.x;
    int base = b * SCAN_CHUNK + t * 4;
    int loc[4]; int ts = 0;
#pragma unroll
    for (int k = 0; k < 4; k++) {
        loc[k] = (base + k < N_NODES) ? g_cnt[base + k] : 0;
        ts += loc[k];
    }
    sm[t] = ts; __syncthreads();
    for (int o = 1; o < 256; o <<= 1) {
        int v = (t >= o) ? sm[t - o] : 0;
        __syncthreads();
        sm[t] += v;
        __syncthreads();
    }
    int pfx = g_bbase[b] + sm[t] - ts;   // exclusive
#pragma unroll
    for (int k = 0; k < 4; k++) {
        if (base + k < N_NODES) { g_off[base + k] = pfx; g_cur[base + k] = pfx; pfx += loc[k]; }
    }
}

__global__ void fill_kernel(const int* __restrict__ ei) {
    int e = blockIdx.x * blockDim.x + threadIdx.x;
    if (e < N_EDGES) {
        int dst = ei[N_EDGES + e];
        int p = atomicAdd(&g_cur[dst], 1);
        g_csr[p] = ei[e];
    }
}

// ---------------- layer-1 gather: agg1[i] = inv[i] * sum_{e->i} x[src] --------
// one warp per node; 128 floats = 1 float4 per lane
__global__ __launch_bounds__(256) void gather1_kernel(const float* __restrict__ x) {
    int node = blockIdx.x * 8 + (threadIdx.x >> 5);
    if (node >= N_NODES) return;
    int lane = threadIdx.x & 31;
    int s = g_off[node], e = g_off[node + 1];
    const float4* x4 = (const float4*)x;
    float4 acc = make_float4(0.f, 0.f, 0.f, 0.f);
    int j = s;
    for (; j + 1 < e; j += 2) {
        int s0 = g_csr[j], s1 = g_csr[j + 1];
        float4 v0 = x4[(size_t)s0 * 32 + lane];
        float4 v1 = x4[(size_t)s1 * 32 + lane];
        acc.x += v0.x + v1.x; acc.y += v0.y + v1.y;
        acc.z += v0.z + v1.z; acc.w += v0.w + v1.w;
    }
    if (j < e) {
        float4 v0 = x4[(size_t)g_csr[j] * 32 + lane];
        acc.x += v0.x; acc.y += v0.y; acc.z += v0.z; acc.w += v0.w;
    }
    float iv = g_inv[node];
    acc.x *= iv; acc.y *= iv; acc.z *= iv; acc.w *= iv;
    ((float4*)g_agg1)[(size_t)node * 32 + lane] = acc;
}

// ---------------- layer-2 gather: agg2[i] = inv[i] * sum_{e->i} h1[src] ------
// one warp per node; 256 floats = 2 float4 per lane
__global__ __launch_bounds__(256) void gather2_kernel() {
    int node = blockIdx.x * 8 + (threadIdx.x >> 5);
    if (node >= N_NODES) return;
    int lane = threadIdx.x & 31;
    int s = g_off[node], e = g_off[node + 1];
    const float4* h4 = (const float4*)g_h1;
    float4 a0 = make_float4(0.f, 0.f, 0.f, 0.f);
    float4 a1 = make_float4(0.f, 0.f, 0.f, 0.f);
    int j = s;
    for (; j + 1 < e; j += 2) {
        int s0 = g_csr[j], s1 = g_csr[j + 1];
        float4 u0 = h4[(size_t)s0 * 64 + lane];
        float4 u1 = h4[(size_t)s0 * 64 + lane + 32];
        float4 v0 = h4[(size_t)s1 * 64 + lane];
        float4 v1 = h4[(size_t)s1 * 64 + lane + 32];
        a0.x += u0.x + v0.x; a0.y += u0.y + v0.y; a0.z += u0.z + v0.z; a0.w += u0.w + v0.w;
        a1.x += u1.x + v1.x; a1.y += u1.y + v1.y; a1.z += u1.z + v1.z; a1.w += u1.w + v1.w;
    }
    if (j < e) {
        int s0 = g_csr[j];
        float4 u0 = h4[(size_t)s0 * 64 + lane];
        float4 u1 = h4[(size_t)s0 * 64 + lane + 32];
        a0.x += u0.x; a0.y += u0.y; a0.z += u0.z; a0.w += u0.w;
        a1.x += u1.x; a1.y += u1.y; a1.z += u1.z; a1.w += u1.w;
    }
    float iv = g_inv[node];
    a0.x *= iv; a0.y *= iv; a0.z *= iv; a0.w *= iv;
    a1.x *= iv; a1.y *= iv; a1.z *= iv; a1.w *= iv;
    float4* o = (float4*)g_agg2 + (size_t)node * 64;
    o[lane] = a0;
    o[lane + 32] = a1;
}

// ---------------- fused layer-1 GEMM via TF32 mma.sync ----------------
#define BM 128
#define BN 128
#define BK 16
#define A_PITCH 20
#define B_PITCH 136

__global__ __launch_bounds__(256, 2) void gemm1_tc_kernel(const float* __restrict__ x,
                                                          const float* __restrict__ W1l,
                                                          const float* __restrict__ W1r,
                                                          const float* __restrict__ b1) {
    __shared__ float As[2][BM][A_PITCH];
    __shared__ float Bs[2][BK][B_PITCH];

    const int tid    = threadIdx.x;
    const int lane   = tid & 31;
    const int wid    = tid >> 5;
    const int warp_m = wid & 3;
    const int warp_n = wid >> 2;
    const int g      = lane >> 2;
    const int t      = lane & 3;

    const int rowBase = blockIdx.x * BM;
    const int colBase = blockIdx.y * BN;

    const int a_r  = tid >> 2;
    const int a_c4 = tid & 3;

    float acc[2][8][4];
#pragma unroll
    for (int mt = 0; mt < 2; mt++)
#pragma unroll
        for (int nt = 0; nt < 8; nt++)
#pragma unroll
            for (int c = 0; c < 4; c++) acc[mt][nt][c] = 0.f;

    float4 aR[2], bR[2];

    auto fetch = [&](int kc) {
        const float* Asrc = (kc < 8) ? g_agg1 : x;
        const float* Bsrc = (kc < 8) ? W1l : W1r;
        int kb = (kc & 7) * BK;
#pragma unroll
        for (int p = 0; p < 2; p++) {
            int r = rowBase + p * 64 + a_r;
            r = min(r, N_NODES - 1);
            aR[p] = *(const float4*)(Asrc + (size_t)r * D_IN + kb + a_c4 * 4);
        }
#pragma unroll
        for (int q = 0; q < 2; q++) {
            int lin = q * 256 + tid;
            int r  = lin >> 5;
            int c4 = lin & 31;
            bR[q] = *(const float4*)(Bsrc + (size_t)(kb + r) * HIDDEN + colBase + c4 * 4);
        }
    };

    auto store = [&](int buf) {
#pragma unroll
        for (int p = 0; p < 2; p++) {
            float* d = &As[buf][p * 64 + a_r][a_c4 * 4];
            d[0] = to_tf32(aR[p].x); d[1] = to_tf32(aR[p].y);
            d[2] = to_tf32(aR[p].z); d[3] = to_tf32(aR[p].w);
        }
#pragma unroll
        for (int q = 0; q < 2; q++) {
            int lin = q * 256 + tid;
            int r  = lin >> 5;
            int c4 = lin & 31;
            float* d = &Bs[buf][r][c4 * 4];
            d[0] = to_tf32(bR[q].x); d[1] = to_tf32(bR[q].y);
            d[2] = to_tf32(bR[q].z); d[3] = to_tf32(bR[q].w);
        }
    };

    fetch(0);
    store(0);
    __syncthreads();

    int buf = 0;
    for (int kc = 0; kc < 16; kc++) {
        if (kc < 15) fetch(kc + 1);
#pragma unroll
        for (int ks = 0; ks < 2; ks++) {
            const int k0 = ks * 8;
            uint32_t af[2][4];
#pragma unroll
            for (int mt = 0; mt < 2; mt++) {
                int m0 = warp_m * 32 + mt * 16;
                af[mt][0] = __float_as_uint(As[buf][m0 + g    ][k0 + t    ]);
                af[mt][1] = __float_as_uint(As[buf][m0 + g + 8][k0 + t    ]);
                af[mt][2] = __float_as_uint(As[buf][m0 + g    ][k0 + t + 4]);
                af[mt][3] = __float_as_uint(As[buf][m0 + g + 8][k0 + t + 4]);
            }
            uint32_t bf[8][2];
#pragma unroll
            for (int nt = 0; nt < 8; nt++) {
                int n0 = warp_n * 64 + nt * 8;
                bf[nt][0] = __float_as_uint(Bs[buf][k0 + t    ][n0 + g]);
                bf[nt][1] = __float_as_uint(Bs[buf][k0 + t + 4][n0 + g]);
            }
#pragma unroll
            for (int mt = 0; mt < 2; mt++)
#pragma unroll
                for (int nt = 0; nt < 8; nt++) {
                    asm volatile(
                        "mma.sync.aligned.m16n8k8.row.col.f32.tf32.tf32.f32 "
                        "{%0,%1,%2,%3}, {%4,%5,%6,%7}, {%8,%9}, {%0,%1,%2,%3};"
                        : "+f"(acc[mt][nt][0]), "+f"(acc[mt][nt][1]),
                          "+f"(acc[mt][nt][2]), "+f"(acc[mt][nt][3])
                        : "r"(af[mt][0]), "r"(af[mt][1]), "r"(af[mt][2]), "r"(af[mt][3]),
                          "r"(bf[nt][0]), "r"(bf[nt][1]));
                }
        }
        if (kc < 15) {
            buf ^= 1;
            store(buf);
            __syncthreads();
        }
    }

#pragma unroll
    for (int mt = 0; mt < 2; mt++) {
        int row0 = rowBase + warp_m * 32 + mt * 16 + g;
        int row1 = row0 + 8;
#pragma unroll
        for (int nt = 0; nt < 8; nt++) {
            int col = colBase + warp_n * 64 + nt * 8 + 2 * t;
            float bx = b1[col], by = b1[col + 1];
            if (row0 < N_NODES) {
                float2 o;
                o.x = fmaxf(acc[mt][nt][0] + bx, 0.f);
                o.y = fmaxf(acc[mt][nt][1] + by, 0.f);
                *(float2*)(g_h1 + (size_t)row0 * HIDDEN + col) = o;
            }
            if (row1 < N_NODES) {
                float2 o;
                o.x = fmaxf(acc[mt][nt][2] + bx, 0.f);
                o.y = fmaxf(acc[mt][nt][3] + by, 0.f);
                *(float2*)(g_h1 + (size_t)row1 * HIDDEN + col) = o;
            }
        }
    }
}

// ---------------- pooling: per-graph contiguous segment sums ----------------
__device__ __forceinline__ int lower_bound_i(const int* a, int n, int v) {
    int lo = 0, hi = n;
    while (lo < hi) {
        int mid = (lo + hi) >> 1;
        if (a[mid] < v) lo = mid + 1; else hi = mid;
    }
    return lo;
}

__global__ __launch_bounds__(256) void pool_kernel(const int* __restrict__ batch) {
    int g = blockIdx.x;
    int t = threadIdx.x;
    int start = lower_bound_i(batch, N_NODES, g);
    int end   = lower_bound_i(batch, N_NODES, g + 1);

    float sh = 0.f, sa = 0.f;
    int i = start;
    for (; i + 3 < end; i += 4) {
        float h0 = g_h1[(size_t)(i + 0) * HIDDEN + t];
        float h1v = g_h1[(size_t)(i + 1) * HIDDEN + t];
        float h2 = g_h1[(size_t)(i + 2) * HIDDEN + t];
        float h3 = g_h1[(size_t)(i + 3) * HIDDEN + t];
        float a0 = g_agg2[(size_t)(i + 0) * HIDDEN + t];
        float a1 = g_agg2[(size_t)(i + 1) * HIDDEN + t];
        float a2 = g_agg2[(size_t)(i + 2) * HIDDEN + t];
        float a3 = g_agg2[(size_t)(i + 3) * HIDDEN + t];
        sh += (h0 + h1v) + (h2 + h3);
        sa += (a0 + a1) + (a2 + a3);
    }
    for (; i < end; i++) {
        sh += g_h1[(size_t)i * HIDDEN + t];
        sa += g_agg2[(size_t)i * HIDDEN + t];
    }
    g_Ph[g * HIDDEN + t] = sh;
    g_Pa[g * HIDDEN + t] = sa;
    if (t == 0) g_ng[g] = (float)(end - start);
}

// ---------------- final tiny GEMM: out = Pa@W2l + Ph@W2r + ng*b2 -------------
__global__ __launch_bounds__(256) void final_kernel(const float* __restrict__ W2l,
                                                    const float* __restrict__ W2r,
                                                    const float* __restrict__ b2,
                                                    float* __restrict__ out) {
    __shared__ float pa[HIDDEN], ph[HIDDEN];
    int g = blockIdx.x;
    int t = threadIdx.x;
    pa[t] = g_Pa[g * HIDDEN + t];
    ph[t] = g_Ph[g * HIDDEN + t];
    __syncthreads();
    float acc = g_ng[g] * b2[t];
#pragma unroll 8
    for (int k = 0; k < HIDDEN; k++) {
        acc += pa[k] * W2l[k * OUT_D + t] + ph[k] * W2r[k * OUT_D + t];
    }
    out[g * OUT_D + t] = acc;
}

// ---------------- launch ----------------
extern "C" void kernel_launch(void* const* d_in, const int* in_sizes, int n_in,
                              void* d_out, int out_size) {
    const float* x     = (const float*)d_in[0];
    const int*   ei    = (const int*)d_in[1];
    const int*   batch = (const int*)d_in[2];
    const float* W1l   = (const float*)d_in[3];
    const float* b1    = (const float*)d_in[4];
    const float* W1r   = (const float*)d_in[5];
    const float* W2l   = (const float*)d_in[6];
    const float* b2    = (const float*)d_in[7];
    const float* W2r   = (const float*)d_in[8];
    float* out = (float*)d_out;

    // CSR build
    zero_cnt_kernel<<<(N_NODES + 255) / 256, 256>>>();
    count_kernel<<<(N_EDGES + 255) / 256, 256>>>(ei);
    inv_kernel<<<(N_NODES + 255) / 256, 256>>>();
    scan1_kernel<<<NBLK_SCAN, 256>>>();
    scan2_kernel<<<1, 32>>>();
    scan3_kernel<<<NBLK_SCAN, 256>>>();
    fill_kernel<<<(N_EDGES + 255) / 256, 256>>>(ei);

    // layer 1
    gather1_kernel<<<(N_NODES + 7) / 8, 256>>>(x);
    dim3 gemmGrid((N_NODES + BM - 1) / BM, HIDDEN / BN);
    gemm1_tc_kernel<<<gemmGrid, 256>>>(x, W1l, W1r, b1);

    // layer 2 (aggregation only; projection folded after pooling)
    gather2_kernel<<<(N_NODES + 7) / 8, 256>>>();

    pool_kernel<<<NUM_GRAPHS, 256>>>(batch);
    final_kernel<<<NUM_GRAPHS, 256>>>(W2l, W2r, b2, out);
}

// round 6
// speedup vs baseline: 2.5790x; 1.1709x over previous
#include <cuda_runtime.h>
#include <cstdint>

#define N_NODES    100000
#define N_EDGES    640000
#define D_IN       128
#define HIDDEN     256
#define H2         (HIDDEN / 2)     // 128 bf16x2 words per h1 row
#define OUT_D      256
#define NUM_GRAPHS 256
#define QSPLIT     8                // CTAs per graph in fused pool
#define SCAN_CHUNK 1024
#define NBLK_SCAN  ((N_NODES + SCAN_CHUNK - 1) / SCAN_CHUNK)   // 98

// ---------------- scratch (device globals; no allocs allowed) ----------------
__device__ __align__(16) float    g_agg1[N_NODES * D_IN];   // mean-agg of x
__device__ __align__(16) unsigned g_h1b [N_NODES * H2];     // relu layer-1 out, bf16x2
__device__ __align__(16) int      g_cnt [N_NODES];
__device__ __align__(16) float    g_inv [N_NODES];
__device__ __align__(16) int      g_off [N_NODES + 1];
__device__ __align__(16) int      g_cur [N_NODES];
__device__ __align__(16) int      g_csr [N_EDGES];
__device__ __align__(16) int      g_bsum [NBLK_SCAN];
__device__ __align__(16) int      g_bbase[NBLK_SCAN];
__device__ __align__(16) float    g_Php[QSPLIT * NUM_GRAPHS * HIDDEN]; // partial segsum(h1)
__device__ __align__(16) float    g_Pap[QSPLIT * NUM_GRAPHS * HIDDEN]; // partial segsum(agg2)
__device__ __align__(16) float    g_ng [NUM_GRAPHS];

__device__ __forceinline__ float to_tf32(float x) {
    uint32_t u;
    asm("cvt.rna.tf32.f32 %0, %1;" : "=r"(u) : "f"(x));
    return __uint_as_float(u);
}

// pack: low 16 bits <- lo, high 16 bits <- hi
__device__ __forceinline__ unsigned pack_bf16x2(float lo, float hi) {
    unsigned u;
    asm("cvt.rn.bf16x2.f32 %0, %1, %2;" : "=r"(u) : "f"(hi), "f"(lo));
    return u;
}
__device__ __forceinline__ float2 unpack_bf16x2(unsigned u) {
    float2 f;
    f.x = __uint_as_float(u << 16);
    f.y = __uint_as_float(u & 0xFFFF0000u);
    return f;
}

// ---------------- CSR build ----------------
__global__ void zero_cnt_kernel() {
    int i = blockIdx.x * blockDim.x + threadIdx.x;
    if (i < N_NODES) g_cnt[i] = 0;
}

__global__ void count_kernel(const int* __restrict__ ei) {
    int e = blockIdx.x * blockDim.x + threadIdx.x;
    if (e < N_EDGES) atomicAdd(&g_cnt[ei[N_EDGES + e]], 1);
}

__global__ void inv_kernel() {
    int i = blockIdx.x * blockDim.x + threadIdx.x;
    if (i < N_NODES) g_inv[i] = 1.0f / (float)max(g_cnt[i], 1);
}

__global__ __launch_bounds__(256) void scan1_kernel() {
    __shared__ int sm[256];
    int b = blockIdx.x, t = threadIdx.x;
    int s = 0;
#pragma unroll
    for (int k = 0; k < 4; k++) {
        int i = b * SCAN_CHUNK + k * 256 + t;
        if (i < N_NODES) s += g_cnt[i];
    }
    sm[t] = s; __syncthreads();
    for (int o = 128; o > 0; o >>= 1) {
        if (t < o) sm[t] += sm[t + o];
        __syncthreads();
    }
    if (t == 0) g_bsum[b] = sm[0];
}

__global__ void scan2_kernel() {
    if (threadIdx.x == 0) {
        int run = 0;
        for (int b = 0; b < NBLK_SCAN; b++) { g_bbase[b] = run; run += g_bsum[b]; }
        g_off[N_NODES] = N_EDGES;
    }
}

__global__ __launch_bounds__(256) void scan3_kernel() {
    __shared__ int sm[256];
    int b = blockIdx.x, t = threadIdx.x;
    int base = b * SCAN_CHUNK + t * 4;
    int loc[4]; int ts = 0;
#pragma unroll
    for (int k = 0; k < 4; k++) {
        loc[k] = (base + k < N_NODES) ? g_cnt[base + k] : 0;
        ts += loc[k];
    }
    sm[t] = ts; __syncthreads();
    for (int o = 1; o < 256; o <<= 1) {
        int v = (t >= o) ? sm[t - o] : 0;
        __syncthreads();
        sm[t] += v;
        __syncthreads();
    }
    int pfx = g_bbase[b] + sm[t] - ts;
#pragma unroll
    for (int k = 0; k < 4; k++) {
        if (base + k < N_NODES) { g_off[base + k] = pfx; g_cur[base + k] = pfx; pfx += loc[k]; }
    }
}

__global__ void fill_kernel(const int* __restrict__ ei) {
    int e = blockIdx.x * blockDim.x + threadIdx.x;
    if (e < N_EDGES) {
        int dst = ei[N_EDGES + e];
        int p = atomicAdd(&g_cur[dst], 1);
        g_csr[p] = ei[e];
    }
}

// ---------------- layer-1 gather: agg1[i] = inv[i] * sum_{e->i} x[src] --------
__global__ __launch_bounds__(256) void gather1_kernel(const float* __restrict__ x) {
    int node = blockIdx.x * 8 + (threadIdx.x >> 5);
    if (node >= N_NODES) return;
    int lane = threadIdx.x & 31;
    int s = g_off[node], e = g_off[node + 1];
    const float4* x4 = (const float4*)x;
    float4 acc = make_float4(0.f, 0.f, 0.f, 0.f);
    int j = s;
    for (; j + 1 < e; j += 2) {
        int s0 = g_csr[j], s1 = g_csr[j + 1];
        float4 v0 = x4[(size_t)s0 * 32 + lane];
        float4 v1 = x4[(size_t)s1 * 32 + lane];
        acc.x += v0.x + v1.x; acc.y += v0.y + v1.y;
        acc.z += v0.z + v1.z; acc.w += v0.w + v1.w;
    }
    if (j < e) {
        float4 v0 = x4[(size_t)g_csr[j] * 32 + lane];
        acc.x += v0.x; acc.y += v0.y; acc.z += v0.z; acc.w += v0.w;
    }
    float iv = g_inv[node];
    acc.x *= iv; acc.y *= iv; acc.z *= iv; acc.w *= iv;
    ((float4*)g_agg1)[(size_t)node * 32 + lane] = acc;
}

// ---------------- fused layer-1 GEMM via TF32 mma.sync ----------------
#define BM 128
#define BN 128
#define BK 16
#define A_PITCH 20
#define B_PITCH 136

__global__ __launch_bounds__(256, 2) void gemm1_tc_kernel(const float* __restrict__ x,
                                                          const float* __restrict__ W1l,
                                                          const float* __restrict__ W1r,
                                                          const float* __restrict__ b1) {
    __shared__ float As[2][BM][A_PITCH];
    __shared__ float Bs[2][BK][B_PITCH];

    const int tid    = threadIdx.x;
    const int lane   = tid & 31;
    const int wid    = tid >> 5;
    const int warp_m = wid & 3;
    const int warp_n = wid >> 2;
    const int g      = lane >> 2;
    const int t      = lane & 3;

    const int rowBase = blockIdx.x * BM;
    const int colBase = blockIdx.y * BN;

    const int a_r  = tid >> 2;
    const int a_c4 = tid & 3;

    float acc[2][8][4];
#pragma unroll
    for (int mt = 0; mt < 2; mt++)
#pragma unroll
        for (int nt = 0; nt < 8; nt++)
#pragma unroll
            for (int c = 0; c < 4; c++) acc[mt][nt][c] = 0.f;

    float4 aR[2], bR[2];

    auto fetch = [&](int kc) {
        const float* Asrc = (kc < 8) ? g_agg1 : x;
        const float* Bsrc = (kc < 8) ? W1l : W1r;
        int kb = (kc & 7) * BK;
#pragma unroll
        for (int p = 0; p < 2; p++) {
            int r = rowBase + p * 64 + a_r;
            r = min(r, N_NODES - 1);
            aR[p] = *(const float4*)(Asrc + (size_t)r * D_IN + kb + a_c4 * 4);
        }
#pragma unroll
        for (int q = 0; q < 2; q++) {
            int lin = q * 256 + tid;
            int r  = lin >> 5;
            int c4 = lin & 31;
            bR[q] = *(const float4*)(Bsrc + (size_t)(kb + r) * HIDDEN + colBase + c4 * 4);
        }
    };

    auto store = [&](int buf) {
#pragma unroll
        for (int p = 0; p < 2; p++) {
            float* d = &As[buf][p * 64 + a_r][a_c4 * 4];
            d[0] = to_tf32(aR[p].x); d[1] = to_tf32(aR[p].y);
            d[2] = to_tf32(aR[p].z); d[3] = to_tf32(aR[p].w);
        }
#pragma unroll
        for (int q = 0; q < 2; q++) {
            int lin = q * 256 + tid;
            int r  = lin >> 5;
            int c4 = lin & 31;
            float* d = &Bs[buf][r][c4 * 4];
            d[0] = to_tf32(bR[q].x); d[1] = to_tf32(bR[q].y);
            d[2] = to_tf32(bR[q].z); d[3] = to_tf32(bR[q].w);
        }
    };

    fetch(0);
    store(0);
    __syncthreads();

    int buf = 0;
    for (int kc = 0; kc < 16; kc++) {
        if (kc < 15) fetch(kc + 1);
#pragma unroll
        for (int ks = 0; ks < 2; ks++) {
            const int k0 = ks * 8;
            uint32_t af[2][4];
#pragma unroll
            for (int mt = 0; mt < 2; mt++) {
                int m0 = warp_m * 32 + mt * 16;
                af[mt][0] = __float_as_uint(As[buf][m0 + g    ][k0 + t    ]);
                af[mt][1] = __float_as_uint(As[buf][m0 + g + 8][k0 + t    ]);
                af[mt][2] = __float_as_uint(As[buf][m0 + g    ][k0 + t + 4]);
                af[mt][3] = __float_as_uint(As[buf][m0 + g + 8][k0 + t + 4]);
            }
            uint32_t bf[8][2];
#pragma unroll
            for (int nt = 0; nt < 8; nt++) {
                int n0 = warp_n * 64 + nt * 8;
                bf[nt][0] = __float_as_uint(Bs[buf][k0 + t    ][n0 + g]);
                bf[nt][1] = __float_as_uint(Bs[buf][k0 + t + 4][n0 + g]);
            }
#pragma unroll
            for (int mt = 0; mt < 2; mt++)
#pragma unroll
                for (int nt = 0; nt < 8; nt++) {
                    asm volatile(
                        "mma.sync.aligned.m16n8k8.row.col.f32.tf32.tf32.f32 "
                        "{%0,%1,%2,%3}, {%4,%5,%6,%7}, {%8,%9}, {%0,%1,%2,%3};"
                        : "+f"(acc[mt][nt][0]), "+f"(acc[mt][nt][1]),
                          "+f"(acc[mt][nt][2]), "+f"(acc[mt][nt][3])
                        : "r"(af[mt][0]), "r"(af[mt][1]), "r"(af[mt][2]), "r"(af[mt][3]),
                          "r"(bf[nt][0]), "r"(bf[nt][1]));
                }
        }
        if (kc < 15) {
            buf ^= 1;
            store(buf);
            __syncthreads();
        }
    }

    // epilogue: bias + relu + bf16x2 store
#pragma unroll
    for (int mt = 0; mt < 2; mt++) {
        int row0 = rowBase + warp_m * 32 + mt * 16 + g;
        int row1 = row0 + 8;
#pragma unroll
        for (int nt = 0; nt < 8; nt++) {
            int col = colBase + warp_n * 64 + nt * 8 + 2 * t;   // even
            float bx = b1[col], by = b1[col + 1];
            if (row0 < N_NODES) {
                float ox = fmaxf(acc[mt][nt][0] + bx, 0.f);
                float oy = fmaxf(acc[mt][nt][1] + by, 0.f);
                g_h1b[(size_t)row0 * H2 + (col >> 1)] = pack_bf16x2(ox, oy);
            }
            if (row1 < N_NODES) {
                float ox = fmaxf(acc[mt][nt][2] + bx, 0.f);
                float oy = fmaxf(acc[mt][nt][3] + by, 0.f);
                g_h1b[(size_t)row1 * H2 + (col >> 1)] = pack_bf16x2(ox, oy);
            }
        }
    }
}

// ---------------- fused layer-2 aggregation + pooling ----------------
// Pa[g] = sum_{i in g} inv[i] * sum_{j in N(i)} h1[j]   (agg2 never materialized)
// Ph[g] = sum_{i in g} h1[i]
// QSPLIT CTAs per graph (disjoint node subranges), 128 threads = 128 bf16x2 cols.
__device__ __forceinline__ int lower_bound_i(const int* a, int n, int v) {
    int lo = 0, hi = n;
    while (lo < hi) {
        int mid = (lo + hi) >> 1;
        if (a[mid] < v) lo = mid + 1; else hi = mid;
    }
    return lo;
}

__global__ __launch_bounds__(128) void fusedpool_kernel(const int* __restrict__ batch) {
    int gq = blockIdx.x;
    int g  = gq >> 3;
    int q  = gq & 7;
    int t  = threadIdx.x;   // col-pair 0..127

    int s0 = lower_bound_i(batch, N_NODES, g);
    int e0 = lower_bound_i(batch, N_NODES, g + 1);
    int n  = e0 - s0;
    int qs = s0 + (int)((long long)n * q / QSPLIT);
    int qe = s0 + (int)((long long)n * (q + 1) / QSPLIT);

    float ahx = 0.f, ahy = 0.f, aax = 0.f, aay = 0.f;

    for (int i = qs; i < qe; i++) {
        float2 hf = unpack_bf16x2(g_h1b[(size_t)i * H2 + t]);
        ahx += hf.x; ahy += hf.y;
        float s = g_inv[i];
        int p  = g_off[i];
        int p1 = g_off[i + 1];
        float sx = 0.f, sy = 0.f;
        for (; p + 3 < p1; p += 4) {
            int j0 = g_csr[p], j1 = g_csr[p + 1], j2 = g_csr[p + 2], j3 = g_csr[p + 3];
            float2 f0 = unpack_bf16x2(g_h1b[(size_t)j0 * H2 + t]);
            float2 f1 = unpack_bf16x2(g_h1b[(size_t)j1 * H2 + t]);
            float2 f2 = unpack_bf16x2(g_h1b[(size_t)j2 * H2 + t]);
            float2 f3 = unpack_bf16x2(g_h1b[(size_t)j3 * H2 + t]);
            sx += (f0.x + f1.x) + (f2.x + f3.x);
            sy += (f0.y + f1.y) + (f2.y + f3.y);
        }
        for (; p < p1; p++) {
            float2 f0 = unpack_bf16x2(g_h1b[(size_t)g_csr[p] * H2 + t]);
            sx += f0.x; sy += f0.y;
        }
        aax += s * sx; aay += s * sy;
    }

    float2* ph = (float2*)&g_Php[(size_t)gq * HIDDEN];
    float2* pa = (float2*)&g_Pap[(size_t)gq * HIDDEN];
    ph[t] = make_float2(ahx, ahy);
    pa[t] = make_float2(aax, aay);
    if (t == 0 && q == 0) g_ng[g] = (float)n;
}

// ---------------- final tiny GEMM: out = Pa@W2l + Ph@W2r + ng*b2 -------------
__global__ __launch_bounds__(256) void final_kernel(const float* __restrict__ W2l,
                                                    const float* __restrict__ W2r,
                                                    const float* __restrict__ b2,
                                                    float* __restrict__ out) {
    __shared__ float pa[HIDDEN], ph[HIDDEN];
    int g = blockIdx.x;
    int t = threadIdx.x;
    float sa = 0.f, sh = 0.f;
#pragma unroll
    for (int q = 0; q < QSPLIT; q++) {
        sa += g_Pap[(size_t)(g * QSPLIT + q) * HIDDEN + t];
        sh += g_Php[(size_t)(g * QSPLIT + q) * HIDDEN + t];
    }
    pa[t] = sa; ph[t] = sh;
    __syncthreads();
    float acc = g_ng[g] * b2[t];
#pragma unroll 8
    for (int k = 0; k < HIDDEN; k++) {
        acc += pa[k] * W2l[k * OUT_D + t] + ph[k] * W2r[k * OUT_D + t];
    }
    out[g * OUT_D + t] = acc;
}

// ---------------- launch ----------------
extern "C" void kernel_launch(void* const* d_in, const int* in_sizes, int n_in,
                              void* d_out, int out_size) {
    const float* x     = (const float*)d_in[0];
    const int*   ei    = (const int*)d_in[1];
    const int*   batch = (const int*)d_in[2];
    const float* W1l   = (const float*)d_in[3];
    const float* b1    = (const float*)d_in[4];
    const float* W1r   = (const float*)d_in[5];
    const float* W2l   = (const float*)d_in[6];
    const float* b2    = (const float*)d_in[7];
    const float* W2r   = (const float*)d_in[8];
    float* out = (float*)d_out;

    // CSR build
    zero_cnt_kernel<<<(N_NODES + 255) / 256, 256>>>();
    count_kernel<<<(N_EDGES + 255) / 256, 256>>>(ei);
    inv_kernel<<<(N_NODES + 255) / 256, 256>>>();
    scan1_kernel<<<NBLK_SCAN, 256>>>();
    scan2_kernel<<<1, 32>>>();
    scan3_kernel<<<NBLK_SCAN, 256>>>();
    fill_kernel<<<(N_EDGES + 255) / 256, 256>>>(ei);

    // layer 1
    gather1_kernel<<<(N_NODES + 7) / 8, 256>>>(x);
    dim3 gemmGrid((N_NODES + BM - 1) / BM, HIDDEN / BN);
    gemm1_tc_kernel<<<gemmGrid, 256>>>(x, W1l, W1r, b1);

    // layer 2 aggregation fused with pooling
    fusedpool_kernel<<<NUM_GRAPHS * QSPLIT, 128>>>(batch);

    final_kernel<<<NUM_GRAPHS, 256>>>(W2l, W2r, b2, out);
}

// round 7
// speedup vs baseline: 2.6811x; 1.0396x over previous
#include <cuda_runtime.h>
#include <cstdint>

#define N_NODES    100000
#define N_EDGES    640000
#define D_IN       128
#define HIDDEN     256
#define H2         (HIDDEN / 2)     // 128 bf16x2 words per h1 row
#define OUT_D      256
#define NUM_GRAPHS 256
#define QSPLIT     8                // CTAs per graph in fused pool
#define SCAN_CHUNK 1024
#define NBLK_SCAN  ((N_NODES + SCAN_CHUNK - 1) / SCAN_CHUNK)   // 98

// ---------------- scratch (device globals; no allocs allowed) ----------------
__device__ __align__(16) float    g_agg1[N_NODES * D_IN];   // mean-agg of x
__device__ __align__(16) unsigned g_h1b [N_NODES * H2];     // relu layer-1 out, bf16x2
__device__ __align__(16) int      g_cnt [N_NODES];
__device__ __align__(16) float    g_inv [N_NODES];
__device__ __align__(16) int      g_off [N_NODES + 1];
__device__ __align__(16) int      g_cur [N_NODES];
__device__ __align__(16) int      g_csr [N_EDGES];
__device__ __align__(16) int      g_bsum [NBLK_SCAN];
__device__ __align__(16) int      g_bbase[NBLK_SCAN];
__device__ __align__(16) float    g_Php[QSPLIT * NUM_GRAPHS * HIDDEN]; // partial segsum(h1)
__device__ __align__(16) float    g_Pap[QSPLIT * NUM_GRAPHS * HIDDEN]; // partial segsum(agg2)
__device__ __align__(16) float    g_ng [NUM_GRAPHS];

// pack: low 16 bits <- lo, high 16 bits <- hi
__device__ __forceinline__ unsigned pack_bf16x2(float lo, float hi) {
    unsigned u;
    asm("cvt.rn.bf16x2.f32 %0, %1, %2;" : "=r"(u) : "f"(hi), "f"(lo));
    return u;
}
__device__ __forceinline__ float2 unpack_bf16x2(unsigned u) {
    float2 f;
    f.x = __uint_as_float(u << 16);
    f.y = __uint_as_float(u & 0xFFFF0000u);
    return f;
}

// ---------------- CSR build ----------------
__global__ void zero_cnt_kernel() {
    int i = blockIdx.x * blockDim.x + threadIdx.x;
    if (i < N_NODES) g_cnt[i] = 0;
}

__global__ void count_kernel(const int* __restrict__ ei) {
    int e = blockIdx.x * blockDim.x + threadIdx.x;
    if (e < N_EDGES) atomicAdd(&g_cnt[ei[N_EDGES + e]], 1);
}

__global__ void inv_kernel() {
    int i = blockIdx.x * blockDim.x + threadIdx.x;
    if (i < N_NODES) g_inv[i] = 1.0f / (float)max(g_cnt[i], 1);
}

__global__ __launch_bounds__(256) void scan1_kernel() {
    __shared__ int sm[256];
    int b = blockIdx.x, t = threadIdx.x;
    int s = 0;
#pragma unroll
    for (int k = 0; k < 4; k++) {
        int i = b * SCAN_CHUNK + k * 256 + t;
        if (i < N_NODES) s += g_cnt[i];
    }
    sm[t] = s; __syncthreads();
    for (int o = 128; o > 0; o >>= 1) {
        if (t < o) sm[t] += sm[t + o];
        __syncthreads();
    }
    if (t == 0) g_bsum[b] = sm[0];
}

__global__ void scan2_kernel() {
    if (threadIdx.x == 0) {
        int run = 0;
        for (int b = 0; b < NBLK_SCAN; b++) { g_bbase[b] = run; run += g_bsum[b]; }
        g_off[N_NODES] = N_EDGES;
    }
}

__global__ __launch_bounds__(256) void scan3_kernel() {
    __shared__ int sm[256];
    int b = blockIdx.x, t = threadIdx.x;
    int base = b * SCAN_CHUNK + t * 4;
    int loc[4]; int ts = 0;
#pragma unroll
    for (int k = 0; k < 4; k++) {
        loc[k] = (base + k < N_NODES) ? g_cnt[base + k] : 0;
        ts += loc[k];
    }
    sm[t] = ts; __syncthreads();
    for (int o = 1; o < 256; o <<= 1) {
        int v = (t >= o) ? sm[t - o] : 0;
        __syncthreads();
        sm[t] += v;
        __syncthreads();
    }
    int pfx = g_bbase[b] + sm[t] - ts;
#pragma unroll
    for (int k = 0; k < 4; k++) {
        if (base + k < N_NODES) { g_off[base + k] = pfx; g_cur[base + k] = pfx; pfx += loc[k]; }
    }
}

__global__ void fill_kernel(const int* __restrict__ ei) {
    int e = blockIdx.x * blockDim.x + threadIdx.x;
    if (e < N_EDGES) {
        int dst = ei[N_EDGES + e];
        int p = atomicAdd(&g_cur[dst], 1);
        g_csr[p] = ei[e];
    }
}

// ---------------- layer-1 gather: agg1[i] = inv[i] * sum_{e->i} x[src] --------
__global__ __launch_bounds__(256) void gather1_kernel(const float* __restrict__ x) {
    int node = blockIdx.x * 8 + (threadIdx.x >> 5);
    if (node >= N_NODES) return;
    int lane = threadIdx.x & 31;
    int s = g_off[node], e = g_off[node + 1];
    const float4* x4 = (const float4*)x;
    float4 acc = make_float4(0.f, 0.f, 0.f, 0.f);
    int j = s;
    for (; j + 1 < e; j += 2) {
        int s0 = g_csr[j], s1 = g_csr[j + 1];
        float4 v0 = x4[(size_t)s0 * 32 + lane];
        float4 v1 = x4[(size_t)s1 * 32 + lane];
        acc.x += v0.x + v1.x; acc.y += v0.y + v1.y;
        acc.z += v0.z + v1.z; acc.w += v0.w + v1.w;
    }
    if (j < e) {
        float4 v0 = x4[(size_t)g_csr[j] * 32 + lane];
        acc.x += v0.x; acc.y += v0.y; acc.z += v0.z; acc.w += v0.w;
    }
    float iv = g_inv[node];
    acc.x *= iv; acc.y *= iv; acc.z *= iv; acc.w *= iv;
    ((float4*)g_agg1)[(size_t)node * 32 + lane] = acc;
}

// ---------------- fused layer-1 GEMM via bf16 mma.sync m16n8k16 ----------------
// h1 = relu( [agg1 | x] (100000 x 256) @ [W1_l ; W1_r] (256 x 256) + b1 )
// CTA tile 128x128, BK=16, double-buffered, 8 warps (4m x 2n), warp tile 32x64.
// SMEM holds bf16x2-packed k-pairs so every fragment load is one LDS.32.
#define BM 128
#define BN 128
#define BK 16
#define AW_PITCH 12    // words per A row (8 + 4 pad): frag bank (12g+t)%32 all distinct
#define BW_PITCH 136   // words per B k-pair row: frag bank (8t+g)%32 all distinct

__global__ __launch_bounds__(256, 2) void gemm1_tc_kernel(const float* __restrict__ x,
                                                          const float* __restrict__ W1l,
                                                          const float* __restrict__ W1r,
                                                          const float* __restrict__ b1) {
    __shared__ unsigned Asw[2][BM][AW_PITCH];     // [m][k/2] bf16x2
    __shared__ unsigned Bsw[2][BK / 2][BW_PITCH]; // [k/2][n] bf16x2 (k-pair packed)

    const int tid    = threadIdx.x;
    const int lane   = tid & 31;
    const int wid    = tid >> 5;
    const int warp_m = wid & 3;
    const int warp_n = wid >> 2;
    const int g      = lane >> 2;
    const int t      = lane & 3;

    const int rowBase = blockIdx.x * BM;
    const int colBase = blockIdx.y * BN;

    // A fetch: 2 threads per row, each loads 8 consecutive k (2 float4)
    const int a_row  = tid >> 1;        // 0..127
    const int a_half = tid & 1;         // k offset 8*a_half
    // B fetch: thread loads rows 2*k2, 2*k2+1 at 4 consecutive n
    const int b_k2 = tid >> 5;          // 0..7
    const int b_c4 = tid & 31;          // n = 4*b_c4

    float acc[2][8][4];
#pragma unroll
    for (int mt = 0; mt < 2; mt++)
#pragma unroll
        for (int nt = 0; nt < 8; nt++)
#pragma unroll
            for (int c = 0; c < 4; c++) acc[mt][nt][c] = 0.f;

    float4 aF0, aF1, bF0, bF1;

    auto fetch = [&](int kc) {   // kc = 0..15, 16 k's each
        const float* Asrc = (kc < 8) ? g_agg1 : x;
        const float* Bsrc = (kc < 8) ? W1l : W1r;
        int kb = (kc & 7) * BK;
        int r = min(rowBase + a_row, N_NODES - 1);
        const float* ap = Asrc + (size_t)r * D_IN + kb + a_half * 8;
        aF0 = *(const float4*)ap;
        aF1 = *(const float4*)(ap + 4);
        const float* bp = Bsrc + (size_t)(kb + 2 * b_k2) * HIDDEN + colBase + b_c4 * 4;
        bF0 = *(const float4*)bp;             // k = 2*k2
        bF1 = *(const float4*)(bp + HIDDEN);  // k = 2*k2+1
    };

    auto store = [&](int buf) {
        uint4 au;
        au.x = pack_bf16x2(aF0.x, aF0.y);
        au.y = pack_bf16x2(aF0.z, aF0.w);
        au.z = pack_bf16x2(aF1.x, aF1.y);
        au.w = pack_bf16x2(aF1.z, aF1.w);
        *(uint4*)&Asw[buf][a_row][a_half * 4] = au;
        uint4 bu;   // word n packs {W[2k2][n], W[2k2+1][n]}
        bu.x = pack_bf16x2(bF0.x, bF1.x);
        bu.y = pack_bf16x2(bF0.y, bF1.y);
        bu.z = pack_bf16x2(bF0.z, bF1.z);
        bu.w = pack_bf16x2(bF0.w, bF1.w);
        *(uint4*)&Bsw[buf][b_k2][b_c4 * 4] = bu;
    };

    fetch(0);
    store(0);
    __syncthreads();

    int buf = 0;
    for (int kc = 0; kc < 16; kc++) {
        if (kc < 15) fetch(kc + 1);
        // A fragments: a0(m=g,k=2t..2t+1) a1(m=g+8) a2(m=g,k=2t+8..) a3(m=g+8,k=2t+8..)
        uint32_t af[2][4];
#pragma unroll
        for (int mt = 0; mt < 2; mt++) {
            int m0 = warp_m * 32 + mt * 16;
            af[mt][0] = Asw[buf][m0 + g    ][t    ];
            af[mt][1] = Asw[buf][m0 + g + 8][t    ];
            af[mt][2] = Asw[buf][m0 + g    ][t + 4];
            af[mt][3] = Asw[buf][m0 + g + 8][t + 4];
        }
        // B fragments: b0(k=2t..2t+1,n=g) b1(k=2t+8..2t+9,n=g)
        uint32_t bf[8][2];
#pragma unroll
        for (int nt = 0; nt < 8; nt++) {
            int n0 = warp_n * 64 + nt * 8;
            bf[nt][0] = Bsw[buf][t    ][n0 + g];
            bf[nt][1] = Bsw[buf][t + 4][n0 + g];
        }
#pragma unroll
        for (int mt = 0; mt < 2; mt++)
#pragma unroll
            for (int nt = 0; nt < 8; nt++) {
                asm volatile(
                    "mma.sync.aligned.m16n8k16.row.col.f32.bf16.bf16.f32 "
                    "{%0,%1,%2,%3}, {%4,%5,%6,%7}, {%8,%9}, {%0,%1,%2,%3};"
                    : "+f"(acc[mt][nt][0]), "+f"(acc[mt][nt][1]),
                      "+f"(acc[mt][nt][2]), "+f"(acc[mt][nt][3])
                    : "r"(af[mt][0]), "r"(af[mt][1]), "r"(af[mt][2]), "r"(af[mt][3]),
                      "r"(bf[nt][0]), "r"(bf[nt][1]));
            }
        if (kc < 15) {
            buf ^= 1;
            store(buf);
            __syncthreads();
        }
    }

    // epilogue: bias + relu + bf16x2 store
#pragma unroll
    for (int mt = 0; mt < 2; mt++) {
        int row0 = rowBase + warp_m * 32 + mt * 16 + g;
        int row1 = row0 + 8;
#pragma unroll
        for (int nt = 0; nt < 8; nt++) {
            int col = colBase + warp_n * 64 + nt * 8 + 2 * t;   // even
            float bx = b1[col], by = b1[col + 1];
            if (row0 < N_NODES) {
                float ox = fmaxf(acc[mt][nt][0] + bx, 0.f);
                float oy = fmaxf(acc[mt][nt][1] + by, 0.f);
                g_h1b[(size_t)row0 * H2 + (col >> 1)] = pack_bf16x2(ox, oy);
            }
            if (row1 < N_NODES) {
                float ox = fmaxf(acc[mt][nt][2] + bx, 0.f);
                float oy = fmaxf(acc[mt][nt][3] + by, 0.f);
                g_h1b[(size_t)row1 * H2 + (col >> 1)] = pack_bf16x2(ox, oy);
            }
        }
    }
}

// ---------------- fused layer-2 aggregation + pooling ----------------
__device__ __forceinline__ int lower_bound_i(const int* a, int n, int v) {
    int lo = 0, hi = n;
    while (lo < hi) {
        int mid = (lo + hi) >> 1;
        if (a[mid] < v) lo = mid + 1; else hi = mid;
    }
    return lo;
}

__global__ __launch_bounds__(128) void fusedpool_kernel(const int* __restrict__ batch) {
    int gq = blockIdx.x;
    int g  = gq >> 3;
    int q  = gq & 7;
    int t  = threadIdx.x;   // col-pair 0..127

    int s0 = lower_bound_i(batch, N_NODES, g);
    int e0 = lower_bound_i(batch, N_NODES, g + 1);
    int n  = e0 - s0;
    int qs = s0 + (int)((long long)n * q / QSPLIT);
    int qe = s0 + (int)((long long)n * (q + 1) / QSPLIT);

    float ahx = 0.f, ahy = 0.f, aax = 0.f, aay = 0.f;

    for (int i = qs; i < qe; i++) {
        float2 hf = unpack_bf16x2(g_h1b[(size_t)i * H2 + t]);
        ahx += hf.x; ahy += hf.y;
        float s = g_inv[i];
        int p  = g_off[i];
        int p1 = g_off[i + 1];
        float sx = 0.f, sy = 0.f;
        for (; p + 3 < p1; p += 4) {
            int j0 = g_csr[p], j1 = g_csr[p + 1], j2 = g_csr[p + 2], j3 = g_csr[p + 3];
            float2 f0 = unpack_bf16x2(g_h1b[(size_t)j0 * H2 + t]);
            float2 f1 = unpack_bf16x2(g_h1b[(size_t)j1 * H2 + t]);
            float2 f2 = unpack_bf16x2(g_h1b[(size_t)j2 * H2 + t]);
            float2 f3 = unpack_bf16x2(g_h1b[(size_t)j3 * H2 + t]);
            sx += (f0.x + f1.x) + (f2.x + f3.x);
            sy += (f0.y + f1.y) + (f2.y + f3.y);
        }
        for (; p < p1; p++) {
            float2 f0 = unpack_bf16x2(g_h1b[(size_t)g_csr[p] * H2 + t]);
            sx += f0.x; sy += f0.y;
        }
        aax += s * sx; aay += s * sy;
    }

    float2* ph = (float2*)&g_Php[(size_t)gq * HIDDEN];
    float2* pa = (float2*)&g_Pap[(size_t)gq * HIDDEN];
    ph[t] = make_float2(ahx, ahy);
    pa[t] = make_float2(aax, aay);
    if (t == 0 && q == 0) g_ng[g] = (float)n;
}

// ---------------- final tiny GEMM: out = Pa@W2l + Ph@W2r + ng*b2 -------------
__global__ __launch_bounds__(256) void final_kernel(const float* __restrict__ W2l,
                                                    const float* __restrict__ W2r,
                                                    const float* __restrict__ b2,
                                                    float* __restrict__ out) {
    __shared__ float pa[HIDDEN], ph[HIDDEN];
    int g = blockIdx.x;
    int t = threadIdx.x;
    float sa = 0.f, sh = 0.f;
#pragma unroll
    for (int q = 0; q < QSPLIT; q++) {
        sa += g_Pap[(size_t)(g * QSPLIT + q) * HIDDEN + t];
        sh += g_Php[(size_t)(g * QSPLIT + q) * HIDDEN + t];
    }
    pa[t] = sa; ph[t] = sh;
    __syncthreads();
    float acc = g_ng[g] * b2[t];
#pragma unroll 8
    for (int k = 0; k < HIDDEN; k++) {
        acc += pa[k] * W2l[k * OUT_D + t] + ph[k] * W2r[k * OUT_D + t];
    }
    out[g * OUT_D + t] = acc;
}

// ---------------- launch ----------------
extern "C" void kernel_launch(void* const* d_in, const int* in_sizes, int n_in,
                              void* d_out, int out_size) {
    const float* x     = (const float*)d_in[0];
    const int*   ei    = (const int*)d_in[1];
    const int*   batch = (const int*)d_in[2];
    const float* W1l   = (const float*)d_in[3];
    const float* b1    = (const float*)d_in[4];
    const float* W1r   = (const float*)d_in[5];
    const float* W2l   = (const float*)d_in[6];
    const float* b2    = (const float*)d_in[7];
    const float* W2r   = (const float*)d_in[8];
    float* out = (float*)d_out;

    // CSR build
    zero_cnt_kernel<<<(N_NODES + 255) / 256, 256>>>();
    count_kernel<<<(N_EDGES + 255) / 256, 256>>>(ei);
    inv_kernel<<<(N_NODES + 255) / 256, 256>>>();
    scan1_kernel<<<NBLK_SCAN, 256>>>();
    scan2_kernel<<<1, 32>>>();
    scan3_kernel<<<NBLK_SCAN, 256>>>();
    fill_kernel<<<(N_EDGES + 255) / 256, 256>>>(ei);

    // layer 1
    gather1_kernel<<<(N_NODES + 7) / 8, 256>>>(x);
    dim3 gemmGrid((N_NODES + BM - 1) / BM, HIDDEN / BN);
    gemm1_tc_kernel<<<gemmGrid, 256>>>(x, W1l, W1r, b1);

    // layer 2 aggregation fused with pooling
    fusedpool_kernel<<<NUM_GRAPHS * QSPLIT, 128>>>(batch);

    final_kernel<<<NUM_GRAPHS, 256>>>(W2l, W2r, b2, out);
}

// round 9
// speedup vs baseline: 2.9141x; 1.0869x over previous
#include <cuda_runtime.h>
#include <cstdint>

#define N_NODES    100000
#define N_EDGES    640000
#define D_IN       128
#define DW         (D_IN / 2)       // 64 bf16x2 words per x row
#define HIDDEN     256
#define H2         (HIDDEN / 2)     // 128 bf16x2 words per h1 row
#define OUT_D      256
#define NUM_GRAPHS 256
#define QSPLIT     16               // CTAs per graph in fused pool
#define SCAN_CHUNK 1024
#define NBLK_SCAN  ((N_NODES + SCAN_CHUNK - 1) / SCAN_CHUNK)   // 98

// ---------------- scratch (device globals; no allocs allowed) ----------------
__device__ __align__(16) unsigned g_xb   [N_NODES * DW];    // x in bf16x2
__device__ __align__(16) unsigned g_agg1b[N_NODES * DW];    // mean-agg of x, bf16x2
__device__ __align__(16) unsigned g_h1b  [N_NODES * H2];    // relu layer-1 out, bf16x2
__device__ __align__(16) int      g_cnt [N_NODES];
__device__ __align__(16) float    g_inv [N_NODES];
__device__ __align__(16) int      g_off [N_NODES + 1];
__device__ __align__(16) int      g_cur [N_NODES];
__device__ __align__(16) int      g_csr [N_EDGES];
__device__ __align__(16) int      g_bsum [NBLK_SCAN];
__device__ __align__(16) int      g_bbase[NBLK_SCAN];
__device__ __align__(16) float    g_Php[QSPLIT * NUM_GRAPHS * HIDDEN];
__device__ __align__(16) float    g_Pap[QSPLIT * NUM_GRAPHS * HIDDEN];
__device__ __align__(16) float    g_ng [NUM_GRAPHS];

// pack: low 16 bits <- lo, high 16 bits <- hi
__device__ __forceinline__ unsigned pack_bf16x2(float lo, float hi) {
    unsigned u;
    asm("cvt.rn.bf16x2.f32 %0, %1, %2;" : "=r"(u) : "f"(hi), "f"(lo));
    return u;
}
__device__ __forceinline__ float2 unpack_bf16x2(unsigned u) {
    float2 f;
    f.x = __uint_as_float(u << 16);
    f.y = __uint_as_float(u & 0xFFFF0000u);
    return f;
}

// ---------------- x -> bf16x2 conversion ----------------
__global__ __launch_bounds__(256) void xconv_kernel(const float* __restrict__ x) {
    size_t i = (size_t)blockIdx.x * blockDim.x + threadIdx.x;   // 8 floats each
    if (i >= (size_t)N_NODES * D_IN / 8) return;
    const float4* xp = (const float4*)x + i * 2;
    float4 f0 = xp[0], f1 = xp[1];
    uint4 u;
    u.x = pack_bf16x2(f0.x, f0.y);
    u.y = pack_bf16x2(f0.z, f0.w);
    u.z = pack_bf16x2(f1.x, f1.y);
    u.w = pack_bf16x2(f1.z, f1.w);
    ((uint4*)g_xb)[i] = u;
}

// ---------------- CSR build ----------------
__global__ void zero_cnt_kernel() {
    int i = blockIdx.x * blockDim.x + threadIdx.x;
    if (i < N_NODES) g_cnt[i] = 0;
}

__global__ void count_kernel(const int* __restrict__ ei) {
    int e = blockIdx.x * blockDim.x + threadIdx.x;
    if (e < N_EDGES) atomicAdd(&g_cnt[ei[N_EDGES + e]], 1);
}

__global__ void inv_kernel() {
    int i = blockIdx.x * blockDim.x + threadIdx.x;
    if (i < N_NODES) g_inv[i] = 1.0f / (float)max(g_cnt[i], 1);
}

__global__ __launch_bounds__(256) void scan1_kernel() {
    __shared__ int sm[256];
    int b = blockIdx.x, t = threadIdx.x;
    int s = 0;
#pragma unroll
    for (int k = 0; k < 4; k++) {
        int i = b * SCAN_CHUNK + k * 256 + t;
        if (i < N_NODES) s += g_cnt[i];
    }
    sm[t] = s; __syncthreads();
    for (int o = 128; o > 0; o >>= 1) {
        if (t < o) sm[t] += sm[t + o];
        __syncthreads();
    }
    if (t == 0) g_bsum[b] = sm[0];
}

__global__ void scan2_kernel() {
    if (threadIdx.x == 0) {
        int run = 0;
        for (int b = 0; b < NBLK_SCAN; b++) { g_bbase[b] = run; run += g_bsum[b]; }
        g_off[N_NODES] = N_EDGES;
    }
}

__global__ __launch_bounds__(256) void scan3_kernel() {
    __shared__ int sm[256];
    int b = blockIdx.x, t = threadIdx.x;
    int base = b * SCAN_CHUNK + t * 4;
    int loc[4]; int ts = 0;
#pragma unroll
    for (int k = 0; k < 4; k++) {
        loc[k] = (base + k < N_NODES) ? g_cnt[base + k] : 0;
        ts += loc[k];
    }
    sm[t] = ts; __syncthreads();
    for (int o = 1; o < 256; o <<= 1) {
        int v = (t >= o) ? sm[t - o] : 0;
        __syncthreads();
        sm[t] += v;
        __syncthreads();
    }
    int pfx = g_bbase[b] + sm[t] - ts;
#pragma unroll
    for (int k = 0; k < 4; k++) {
        if (base + k < N_NODES) { g_off[base + k] = pfx; g_cur[base + k] = pfx; pfx += loc[k]; }
    }
}

__global__ void fill_kernel(const int* __restrict__ ei) {
    int e = blockIdx.x * blockDim.x + threadIdx.x;
    if (e < N_EDGES) {
        int dst = ei[N_EDGES + e];
        int p = atomicAdd(&g_cur[dst], 1);
        g_csr[p] = ei[e];
    }
}

// ---------------- layer-1 gather (bf16 in, bf16 out) ----------------
// one warp per node; 64 words = 2 words per lane
__global__ __launch_bounds__(256) void gather1_kernel() {
    int node = blockIdx.x * 8 + (threadIdx.x >> 5);
    if (node >= N_NODES) return;
    int lane = threadIdx.x & 31;
    int s = g_off[node], e = g_off[node + 1];
    const uint2* x2 = (const uint2*)g_xb;
    float ax = 0.f, ay = 0.f, bx = 0.f, by = 0.f;
    int j = s;
    for (; j + 1 < e; j += 2) {
        int s0 = g_csr[j], s1 = g_csr[j + 1];
        uint2 u0 = x2[(size_t)s0 * 32 + lane];
        uint2 u1 = x2[(size_t)s1 * 32 + lane];
        float2 f0 = unpack_bf16x2(u0.x), f1 = unpack_bf16x2(u0.y);
        float2 g0 = unpack_bf16x2(u1.x), g1 = unpack_bf16x2(u1.y);
        ax += f0.x + g0.x; ay += f0.y + g0.y;
        bx += f1.x + g1.x; by += f1.y + g1.y;
    }
    if (j < e) {
        uint2 u0 = x2[(size_t)g_csr[j] * 32 + lane];
        float2 f0 = unpack_bf16x2(u0.x), f1 = unpack_bf16x2(u0.y);
        ax += f0.x; ay += f0.y; bx += f1.x; by += f1.y;
    }
    float iv = g_inv[node];
    uint2 o;
    o.x = pack_bf16x2(ax * iv, ay * iv);
    o.y = pack_bf16x2(bx * iv, by * iv);
    ((uint2*)g_agg1b)[(size_t)node * 32 + lane] = o;
}

// ---------------- fused layer-1 GEMM via bf16 mma.sync m16n8k16 ----------------
// h1 = relu( [agg1 | x] (100000 x 256) @ [W1_l ; W1_r] (256 x 256) + b1 )
// A-side already bf16x2-packed in gmem -> SMEM load is a raw uint4 copy.
#define BM 128
#define BN 128
#define BK 16
#define AW_PITCH 12    // words per A row (8 + 4 pad)
#define BW_PITCH 136   // words per B k-pair row

__global__ __launch_bounds__(256, 2) void gemm1_tc_kernel(const float* __restrict__ W1l,
                                                          const float* __restrict__ W1r,
                                                          const float* __restrict__ b1) {
    __shared__ unsigned Asw[2][BM][AW_PITCH];     // [m][k/2] bf16x2
    __shared__ unsigned Bsw[2][BK / 2][BW_PITCH]; // [k/2][n] bf16x2 (k-pair packed)

    const int tid    = threadIdx.x;
    const int lane   = tid & 31;
    const int wid    = tid >> 5;
    const int warp_m = wid & 3;
    const int warp_n = wid >> 2;
    const int g      = lane >> 2;
    const int t      = lane & 3;

    const int rowBase = blockIdx.x * BM;
    const int colBase = blockIdx.y * BN;

    // A fetch: 2 threads per row, each loads 4 words (8 k)
    const int a_row  = tid >> 1;
    const int a_half = tid & 1;
    // B fetch: thread loads k-rows 2*k2, 2*k2+1 at 4 consecutive n
    const int b_k2 = tid >> 5;
    const int b_c4 = tid & 31;

    float acc[2][8][4];
#pragma unroll
    for (int mt = 0; mt < 2; mt++)
#pragma unroll
        for (int nt = 0; nt < 8; nt++)
#pragma unroll
            for (int c = 0; c < 4; c++) acc[mt][nt][c] = 0.f;

    uint4 aU;
    float4 bF0, bF1;

    auto fetch = [&](int kc) {   // kc = 0..15, 16 k's each
        const unsigned* Asrc = (kc < 8) ? g_agg1b : g_xb;
        const float*    Bsrc = (kc < 8) ? W1l : W1r;
        int kb = (kc & 7) * BK;
        int r = min(rowBase + a_row, N_NODES - 1);
        aU = *(const uint4*)(Asrc + (size_t)r * DW + (kb >> 1) + a_half * 4);
        const float* bp = Bsrc + (size_t)(kb + 2 * b_k2) * HIDDEN + colBase + b_c4 * 4;
        bF0 = *(const float4*)bp;
        bF1 = *(const float4*)(bp + HIDDEN);
    };

    auto store = [&](int buf) {
        *(uint4*)&Asw[buf][a_row][a_half * 4] = aU;
        uint4 bu;   // word n packs {W[2k2][n], W[2k2+1][n]}
        bu.x = pack_bf16x2(bF0.x, bF1.x);
        bu.y = pack_bf16x2(bF0.y, bF1.y);
        bu.z = pack_bf16x2(bF0.z, bF1.z);
        bu.w = pack_bf16x2(bF0.w, bF1.w);
        *(uint4*)&Bsw[buf][b_k2][b_c4 * 4] = bu;
    };

    fetch(0);
    store(0);
    __syncthreads();

    int buf = 0;
    for (int kc = 0; kc < 16; kc++) {
        if (kc < 15) fetch(kc + 1);
        uint32_t af[2][4];
#pragma unroll
        for (int mt = 0; mt < 2; mt++) {
            int m0 = warp_m * 32 + mt * 16;
            af[mt][0] = Asw[buf][m0 + g    ][t    ];
            af[mt][1] = Asw[buf][m0 + g + 8][t    ];
            af[mt][2] = Asw[buf][m0 + g    ][t + 4];
            af[mt][3] = Asw[buf][m0 + g + 8][t + 4];
        }
        uint32_t bf[8][2];
#pragma unroll
        for (int nt = 0; nt < 8; nt++) {
            int n0 = warp_n * 64 + nt * 8;
            bf[nt][0] = Bsw[buf][t    ][n0 + g];
            bf[nt][1] = Bsw[buf][t + 4][n0 + g];
        }
#pragma unroll
        for (int mt = 0; mt < 2; mt++)
#pragma unroll
            for (int nt = 0; nt < 8; nt++) {
                asm volatile(
                    "mma.sync.aligned.m16n8k16.row.col.f32.bf16.bf16.f32 "
                    "{%0,%1,%2,%3}, {%4,%5,%6,%7}, {%8,%9}, {%0,%1,%2,%3};"
                    : "+f"(acc[mt][nt][0]), "+f"(acc[mt][nt][1]),
                      "+f"(acc[mt][nt][2]), "+f"(acc[mt][nt][3])
                    : "r"(af[mt][0]), "r"(af[mt][1]), "r"(af[mt][2]), "r"(af[mt][3]),
                      "r"(bf[nt][0]), "r"(bf[nt][1]));
            }
        if (kc < 15) {
            buf ^= 1;
            store(buf);
            __syncthreads();
        }
    }

    // epilogue: bias + relu + bf16x2 store
#pragma unroll
    for (int mt = 0; mt < 2; mt++) {
        int row0 = rowBase + warp_m * 32 + mt * 16 + g;
        int row1 = row0 + 8;
#pragma unroll
        for (int nt = 0; nt < 8; nt++) {
            int col = colBase + warp_n * 64 + nt * 8 + 2 * t;
            float bx = b1[col], by = b1[col + 1];
            if (row0 < N_NODES) {
                float ox = fmaxf(acc[mt][nt][0] + bx, 0.f);
                float oy = fmaxf(acc[mt][nt][1] + by, 0.f);
                g_h1b[(size_t)row0 * H2 + (col >> 1)] = pack_bf16x2(ox, oy);
            }
            if (row1 < N_NODES) {
                float ox = fmaxf(acc[mt][nt][2] + bx, 0.f);
                float oy = fmaxf(acc[mt][nt][3] + by, 0.f);
                g_h1b[(size_t)row1 * H2 + (col >> 1)] = pack_bf16x2(ox, oy);
            }
        }
    }
}

// ---------------- fused layer-2 aggregation + pooling ----------------
__device__ __forceinline__ int lower_bound_i(const int* a, int n, int v) {
    int lo = 0, hi = n;
    while (lo < hi) {
        int mid = (lo + hi) >> 1;
        if (a[mid] < v) lo = mid + 1; else hi = mid;
    }
    return lo;
}

__global__ __launch_bounds__(128) void fusedpool_kernel(const int* __restrict__ batch) {
    int gq = blockIdx.x;
    int g  = gq >> 4;
    int q  = gq & (QSPLIT - 1);
    int t  = threadIdx.x;   // col-pair 0..127

    int s0 = lower_bound_i(batch, N_NODES, g);
    int e0 = lower_bound_i(batch, N_NODES, g + 1);
    int n  = e0 - s0;
    int qs = s0 + (int)((long long)n * q / QSPLIT);
    int qe = s0 + (int)((long long)n * (q + 1) / QSPLIT);

    float ahx = 0.f, ahy = 0.f, aax = 0.f, aay = 0.f;

    for (int i = qs; i < qe; i++) {
        float2 hf = unpack_bf16x2(g_h1b[(size_t)i * H2 + t]);
        ahx += hf.x; ahy += hf.y;
        float s = g_inv[i];
        int p  = g_off[i];
        int p1 = g_off[i + 1];
        float sx = 0.f, sy = 0.f;
        for (; p + 3 < p1; p += 4) {
            int j0 = g_csr[p], j1 = g_csr[p + 1], j2 = g_csr[p + 2], j3 = g_csr[p + 3];
            float2 f0 = unpack_bf16x2(g_h1b[(size_t)j0 * H2 + t]);
            float2 f1 = unpack_bf16x2(g_h1b[(size_t)j1 * H2 + t]);
            float2 f2 = unpack_bf16x2(g_h1b[(size_t)j2 * H2 + t]);
            float2 f3 = unpack_bf16x2(g_h1b[(size_t)j3 * H2 + t]);
            sx += (f0.x + f1.x) + (f2.x + f3.x);
            sy += (f0.y + f1.y) + (f2.y + f3.y);
        }
        for (; p < p1; p++) {
            float2 f0 = unpack_bf16x2(g_h1b[(size_t)g_csr[p] * H2 + t]);
            sx += f0.x; sy += f0.y;
        }
        aax += s * sx; aay += s * sy;
    }

    float2* ph = (float2*)&g_Php[(size_t)gq * HIDDEN];
    float2* pa = (float2*)&g_Pap[(size_t)gq * HIDDEN];
    ph[t] = make_float2(ahx, ahy);
    pa[t] = make_float2(aax, aay);
    if (t == 0 && q == 0) g_ng[g] = (float)n;
}

// ---------------- final tiny GEMM: out = Pa@W2l + Ph@W2r + ng*b2 -------------
__global__ __launch_bounds__(256) void final_kernel(const float* __restrict__ W2l,
                                                    const float* __restrict__ W2r,
                                                    const float* __restrict__ b2,
                                                    float* __restrict__ out) {
    __shared__ float pa[HIDDEN], ph[HIDDEN];
    int g = blockIdx.x;
    int t = threadIdx.x;
    float sa = 0.f, sh = 0.f;
#pragma unroll
    for (int q = 0; q < QSPLIT; q++) {
        sa += g_Pap[(size_t)(g * QSPLIT + q) * HIDDEN + t];
        sh += g_Php[(size_t)(g * QSPLIT + q) * HIDDEN + t];
    }
    pa[t] = sa; ph[t] = sh;
    __syncthreads();
    float acc = g_ng[g] * b2[t];
#pragma unroll 8
    for (int k = 0; k < HIDDEN; k++) {
        acc += pa[k] * W2l[k * OUT_D + t] + ph[k] * W2r[k * OUT_D + t];
    }
    out[g * OUT_D + t] = acc;
}

// ---------------- launch ----------------
extern "C" void kernel_launch(void* const* d_in, const int* in_sizes, int n_in,
                              void* d_out, int out_size) {
    const float* x     = (const float*)d_in[0];
    const int*   ei    = (const int*)d_in[1];
    const int*   batch = (const int*)d_in[2];
    const float* W1l   = (const float*)d_in[3];
    const float* b1    = (const float*)d_in[4];
    const float* W1r   = (const float*)d_in[5];
    const float* W2l   = (const float*)d_in[6];
    const float* b2    = (const float*)d_in[7];
    const float* W2r   = (const float*)d_in[8];
    float* out = (float*)d_out;

    // CSR build + x conversion
    zero_cnt_kernel<<<(N_NODES + 255) / 256, 256>>>();
    count_kernel<<<(N_EDGES + 255) / 256, 256>>>(ei);
    xconv_kernel<<<(N_NODES * D_IN / 8 + 255) / 256, 256>>>(x);
    inv_kernel<<<(N_NODES + 255) / 256, 256>>>();
    scan1_kernel<<<NBLK_SCAN, 256>>>();
    scan2_kernel<<<1, 32>>>();
    scan3_kernel<<<NBLK_SCAN, 256>>>();
    fill_kernel<<<(N_EDGES + 255) / 256, 256>>>(ei);

    // layer 1
    gather1_kernel<<<(N_NODES + 7) / 8, 256>>>();
    dim3 gemmGrid((N_NODES + BM - 1) / BM, HIDDEN / BN);
    gemm1_tc_kernel<<<gemmGrid, 256>>>(W1l, W1r, b1);

    // layer 2 aggregation fused with pooling
    fusedpool_kernel<<<NUM_GRAPHS * QSPLIT, 128>>>(batch);

    final_kernel<<<NUM_GRAPHS, 256>>>(W2l, W2r, b2, out);
}